// round 2
// baseline (speedup 1.0000x reference)
#include <cuda_runtime.h>
#include <math.h>

#define B_    64
#define L_    1024
#define D_    128
#define M_    128
#define DM_   512
#define NL_   4
#define H_    8
#define DH_   64
#define PRED_ 96

// ---------------- scratch (device globals; no allocation) ----------------
__device__ float g_xt[(size_t)B_ * D_ * L_];       // x transposed [B,D,L]
__device__ float g_zt[(size_t)B_ * D_ * L_];       // z transposed [B,D,L]
__device__ float g_s[B_ * 2 * D_];                 // [B, 2D] mean|std
__device__ float g_h2[B_ * 32];
__device__ float g_lower[(size_t)B_ * D_ * M_];    // [B,D,M]
__device__ float g_t[(size_t)B_ * D_ * DM_];       // backbone state
__device__ float g_qkv[(size_t)B_ * D_ * 3 * DM_];
__device__ float g_ctx[(size_t)B_ * D_ * DM_];
__device__ float g_y[(size_t)B_ * D_ * DM_];       // proj outputs pre-LN
__device__ float g_mid[(size_t)B_ * D_ * 2 * DM_];
__device__ float g_hp[(size_t)B_ * D_ * M_];

// ---------------- transpose x [B,L,D] -> g_xt [B,D,L] ----------------
__global__ void transpose_x_kernel(const float* __restrict__ x) {
    __shared__ float tile[32][33];
    int b = blockIdx.z;
    int l0 = blockIdx.x * 32, d0 = blockIdx.y * 32;
    int lx = threadIdx.x, ly = threadIdx.y;
#pragma unroll
    for (int r = 0; r < 32; r += 8)
        tile[ly + r][lx] = x[((size_t)b * L_ + (l0 + ly + r)) * D_ + (d0 + lx)];
    __syncthreads();
#pragma unroll
    for (int r = 0; r < 32; r += 8)
        g_xt[((size_t)b * D_ + (d0 + ly + r)) * L_ + (l0 + lx)] = tile[lx][ly + r];
}

// ---------------- copula: bitonic rank -> erfinv z, fused mean/std ----------------
__global__ __launch_bounds__(1024) void copula_kernel() {
    __shared__ float vals[L_];
    __shared__ int   idxs[L_];
    __shared__ int   rankof[L_];
    __shared__ float sq[L_];

    int blk = blockIdx.x;            // b*D + d
    int tid = threadIdx.x;
    const float* col = g_xt + (size_t)blk * L_;

    vals[tid] = col[tid];
    idxs[tid] = tid;
    __syncthreads();

    // bitonic sort ascending by (value, index)  == stable argsort
    for (int k = 2; k <= L_; k <<= 1) {
        for (int j = k >> 1; j > 0; j >>= 1) {
            int ixj = tid ^ j;
            if (ixj > tid) {
                bool up = ((tid & k) == 0);
                float v1 = vals[tid], v2 = vals[ixj];
                int   i1 = idxs[tid], i2 = idxs[ixj];
                bool gt = (v1 > v2) || (v1 == v2 && i1 > i2);
                if (gt == up) {
                    vals[tid] = v2; vals[ixj] = v1;
                    idxs[tid] = i2; idxs[ixj] = i1;
                }
            }
            __syncthreads();
        }
    }
    rankof[idxs[tid]] = tid;         // sorted position of original element
    __syncthreads();

    int r = rankof[tid];             // 0-based; rank = r+1
    float u = ((float)(r + 1) + 0.5f) * (1.0f / (float)L_);
    u = fminf(fmaxf(u, 1e-6f), 1.0f - 1e-6f);
    float zv = erfinvf(2.0f * u - 1.0f) * 1.41421356237309515f;
    g_zt[(size_t)blk * L_ + tid] = zv;

    __syncthreads();                 // vals no longer needed as sort buffer
    vals[tid] = zv;
    sq[tid] = zv * zv;
    __syncthreads();
    for (int s = 512; s > 0; s >>= 1) {
        if (tid < s) { vals[tid] += vals[tid + s]; sq[tid] += sq[tid + s]; }
        __syncthreads();
    }
    if (tid == 0) {
        float sum = vals[0], ssq = sq[0];
        float mean = sum * (1.0f / (float)L_);
        float var = (ssq - sum * sum * (1.0f / (float)L_)) * (1.0f / (float)(L_ - 1));
        int b = blk / D_, d = blk % D_;
        g_s[b * 2 * D_ + d] = mean;
        g_s[b * 2 * D_ + D_ + d] = sqrtf(fmaxf(var, 0.0f));
    }
}

// ---------------- s -> relu(mlp1) -> relu(mlp2) -> g_h2 ----------------
__global__ void mlp12_kernel(const float* __restrict__ w1, const float* __restrict__ b1,
                             const float* __restrict__ w2, const float* __restrict__ b2) {
    __shared__ float srow[2 * D_];
    __shared__ float h1[64];
    int b = blockIdx.x, tid = threadIdx.x;   // 64 threads
    for (int i = tid; i < 2 * D_; i += 64) srow[i] = g_s[b * 2 * D_ + i];
    __syncthreads();
    float acc = b1[tid];
    for (int k = 0; k < 2 * D_; ++k) acc += srow[k] * w1[tid * 2 * D_ + k];
    h1[tid] = fmaxf(acc, 0.0f);
    __syncthreads();
    if (tid < 32) {
        float a2 = b2[tid];
        for (int k = 0; k < 64; ++k) a2 += h1[k] * w2[tid * 64 + k];
        g_h2[b * 32 + tid] = fmaxf(a2, 0.0f);
    }
}

// ---------------- lower = h2 @ mlp3_w^T + b  -> [B, D*M] ----------------
__global__ __launch_bounds__(256) void lower_kernel(const float* __restrict__ w3,
                                                    const float* __restrict__ b3) {
    __shared__ float h2s[32];
    __shared__ float wt[256][33];    // padded rows of 32
    int b = blockIdx.x;
    int j0 = blockIdx.y * 256;
    int tid = threadIdx.x;
    if (tid < 32) h2s[tid] = g_h2[b * 32 + tid];
    for (int i = tid; i < 256 * 32; i += 256) {
        int rr = i >> 5, cc = i & 31;
        wt[rr][cc] = w3[(size_t)j0 * 32 + i];
    }
    __syncthreads();
    float acc = b3[j0 + tid];
#pragma unroll
    for (int k = 0; k < 32; ++k) acc += h2s[k] * wt[tid][k];
    g_lower[(size_t)b * (D_ * M_) + j0 + tid] = acc;
}

// ---------------- lam[b] = lower[b] @ lower[b]^T  (writes into d_out) ----------------
__global__ __launch_bounds__(256) void lam_kernel(float* __restrict__ lam_out) {
    extern __shared__ float low[];   // [128][129] padded
    int b = blockIdx.x, tid = threadIdx.x;
    for (int i = tid; i < D_ * M_; i += 256) {
        int rr = i >> 7, cc = i & 127;
        low[rr * 129 + cc] = g_lower[(size_t)b * (D_ * M_) + i];
    }
    __syncthreads();
    for (int e = tid; e < D_ * D_; e += 256) {
        int i = e >> 7, j = e & 127;
        const float* ri = &low[i * 129];
        const float* rj = &low[j * 129];
        float acc = 0.0f;
#pragma unroll 8
        for (int m = 0; m < M_; ++m) acc += ri[m] * rj[m];
        lam_out[(size_t)b * D_ * D_ + e] = acc;
    }
}

// ---------------- generic NT SGEMM: C[M,N] = A[M,K] @ B[N,K]^T + bias ----------------
// All dims: M % 128 == 0, N % 128 == 0, K % 8 == 0 (true for every call here).
__global__ __launch_bounds__(256) void gemm_nt_kernel(
    const float* __restrict__ A, const float* __restrict__ Bm,
    const float* __restrict__ bias, float* __restrict__ C,
    int Mdim, int Ndim, int Kdim, int relu)
{
    __shared__ float As[8][128];
    __shared__ float Bs[8][128];
    int tid = threadIdx.x;
    int n0 = blockIdx.x * 128;
    int m0 = blockIdx.y * 128;
    int tx = tid & 15, ty = tid >> 4;
    int lrow = tid >> 1;
    int lseg = (tid & 1) * 4;

    const float* Aptr = A + (size_t)(m0 + lrow) * Kdim + lseg;
    const float* Bptr = Bm + (size_t)(n0 + lrow) * Kdim + lseg;

    float acc[8][8];
#pragma unroll
    for (int i = 0; i < 8; ++i)
#pragma unroll
        for (int j = 0; j < 8; ++j) acc[i][j] = 0.0f;

    for (int k0 = 0; k0 < Kdim; k0 += 8) {
        float4 av = *(const float4*)(Aptr + k0);
        float4 bv = *(const float4*)(Bptr + k0);
        __syncthreads();
        As[lseg + 0][lrow] = av.x; As[lseg + 1][lrow] = av.y;
        As[lseg + 2][lrow] = av.z; As[lseg + 3][lrow] = av.w;
        Bs[lseg + 0][lrow] = bv.x; Bs[lseg + 1][lrow] = bv.y;
        Bs[lseg + 2][lrow] = bv.z; Bs[lseg + 3][lrow] = bv.w;
        __syncthreads();
#pragma unroll
        for (int kk = 0; kk < 8; ++kk) {
            float4 a0 = *(const float4*)&As[kk][ty * 8];
            float4 a1 = *(const float4*)&As[kk][ty * 8 + 4];
            float4 b0 = *(const float4*)&Bs[kk][tx * 8];
            float4 b1 = *(const float4*)&Bs[kk][tx * 8 + 4];
            float a[8] = {a0.x, a0.y, a0.z, a0.w, a1.x, a1.y, a1.z, a1.w};
            float bb[8] = {b0.x, b0.y, b0.z, b0.w, b1.x, b1.y, b1.z, b1.w};
#pragma unroll
            for (int i = 0; i < 8; ++i)
#pragma unroll
                for (int j = 0; j < 8; ++j) acc[i][j] += a[i] * bb[j];
        }
    }

#pragma unroll
    for (int i = 0; i < 8; ++i) {
        size_t row = (size_t)(m0 + ty * 8 + i) * Ndim + n0 + tx * 8;
#pragma unroll
        for (int j = 0; j < 8; ++j) {
            float v = acc[i][j] + bias[n0 + tx * 8 + j];
            if (relu) v = fmaxf(v, 0.0f);
            C[row + j] = v;
        }
    }
}

// ---------------- fused attention per (b,h): softmax(qk^T/8) v ----------------
#define ATTN_SMEM ((2 * 128 * 64 + 128 * 129) * 4)
__global__ __launch_bounds__(128) void attn_kernel() {
    extern __shared__ float sm[];
    float* ks = sm;                    // [128][64]
    float* vs = sm + 128 * 64;         // [128][64]
    float* sc = sm + 2 * 128 * 64;     // [128][129] padded score rows

    int bh = blockIdx.x;
    int b = bh >> 3, h = bh & 7;
    int tid = threadIdx.x;             // row / token index
    const float* qkvb = g_qkv + (size_t)b * D_ * 3 * DM_;

    const float* krow = qkvb + (size_t)tid * 3 * DM_ + DM_ + h * DH_;
    const float* vrow = qkvb + (size_t)tid * 3 * DM_ + 2 * DM_ + h * DH_;
#pragma unroll
    for (int c = 0; c < DH_; c += 4) {
        *(float4*)&ks[tid * DH_ + c] = *(const float4*)(krow + c);
        *(float4*)&vs[tid * DH_ + c] = *(const float4*)(vrow + c);
    }
    float qv[DH_];
    const float* qrow = qkvb + (size_t)tid * 3 * DM_ + h * DH_;
#pragma unroll
    for (int c = 0; c < DH_; c += 4) {
        float4 q4 = *(const float4*)(qrow + c);
        qv[c] = q4.x; qv[c + 1] = q4.y; qv[c + 2] = q4.z; qv[c + 3] = q4.w;
    }
    __syncthreads();

    float* myrow = &sc[tid * 129];
    float mx = -1e30f;
    for (int j = 0; j < 128; ++j) {
        const float* kj = &ks[j * DH_];
        float a = 0.0f;
#pragma unroll
        for (int c = 0; c < DH_; ++c) a += qv[c] * kj[c];
        a *= 0.125f;
        myrow[j] = a;
        mx = fmaxf(mx, a);
    }
    float ssum = 0.0f;
    for (int j = 0; j < 128; ++j) {
        float e = __expf(myrow[j] - mx);
        myrow[j] = e;
        ssum += e;
    }
    float inv = 1.0f / ssum;

    float acc2[DH_];
#pragma unroll
    for (int c = 0; c < DH_; ++c) acc2[c] = 0.0f;
    for (int j = 0; j < 128; ++j) {
        float p = myrow[j] * inv;
        const float* vj = &vs[j * DH_];
#pragma unroll
        for (int c = 0; c < DH_; ++c) acc2[c] += p * vj[c];
    }
    float* orow = g_ctx + ((size_t)b * D_ + tid) * DM_ + h * DH_;
#pragma unroll
    for (int c = 0; c < DH_; c += 4) {
        float4 o4 = {acc2[c], acc2[c + 1], acc2[c + 2], acc2[c + 3]};
        *(float4*)(orow + c) = o4;
    }
}

// ---------------- residual + layernorm (in-place on g_t) ----------------
__global__ __launch_bounds__(128) void resid_ln_kernel(const float* __restrict__ y,
                                                       const float* __restrict__ gam,
                                                       const float* __restrict__ bet,
                                                       int has_res) {
    int row = blockIdx.x, tid = threadIdx.x;
    float* trow = g_t + (size_t)row * DM_;
    const float* yrow = y + (size_t)row * DM_;
    float v[4];
    float s = 0.0f, sq = 0.0f;
#pragma unroll
    for (int r = 0; r < 4; ++r) {
        int c = tid + r * 128;
        float val = trow[c];
        if (has_res) val += yrow[c];
        v[r] = val; s += val; sq += val * val;
    }
    __shared__ float rs[4], rq[4];
    unsigned lane = tid & 31, wid = tid >> 5;
#pragma unroll
    for (int off = 16; off; off >>= 1) {
        s += __shfl_down_sync(0xffffffffu, s, off);
        sq += __shfl_down_sync(0xffffffffu, sq, off);
    }
    if (lane == 0) { rs[wid] = s; rq[wid] = sq; }
    __syncthreads();
    float S = rs[0] + rs[1] + rs[2] + rs[3];
    float SQ = rq[0] + rq[1] + rq[2] + rq[3];
    float mean = S * (1.0f / (float)DM_);
    float var = SQ * (1.0f / (float)DM_) - mean * mean;
    float rstd = rsqrtf(var + 1e-5f);
#pragma unroll
    for (int r = 0; r < 4; ++r) {
        int c = tid + r * 128;
        trow[c] = (v[r] - mean) * rstd * gam[c] + bet[c];
    }
}

// ---------------- head: y = diag(hp @ (lam@u^T)) broadcast to pred_len ----------------
__global__ __launch_bounds__(128) void head_kernel(const float* __restrict__ u,
                                                   const float* __restrict__ head_bias,
                                                   const float* __restrict__ lam,
                                                   float* __restrict__ out_y) {
    __shared__ float hps[M_];
    __shared__ float red[4];
    __shared__ float ybc;
    int blk = blockIdx.x;              // b*D + i
    int b = blk >> 7, i = blk & 127;
    int tid = threadIdx.x;             // = m
    hps[tid] = g_hp[(size_t)blk * M_ + tid];
    __syncthreads();
    const float* lamb = lam + (size_t)b * D_ * D_;
    float acc = 0.0f;
    for (int k = 0; k < D_; ++k) acc += hps[k] * lamb[(size_t)k * D_ + tid];
    float p = acc * u[(size_t)i * M_ + tid];
    unsigned lane = tid & 31, wid = tid >> 5;
#pragma unroll
    for (int off = 16; off; off >>= 1) p += __shfl_down_sync(0xffffffffu, p, off);
    if (lane == 0) red[wid] = p;
    __syncthreads();
    if (tid == 0) ybc = red[0] + red[1] + red[2] + red[3] + head_bias[i];
    __syncthreads();
    float yv = ybc;
    if (tid < PRED_) out_y[(size_t)blk * PRED_ + tid] = yv;
}

// ---------------- host launcher ----------------
extern "C" void kernel_launch(void* const* d_in, const int* in_sizes, int n_in,
                              void* d_out, int out_size) {
    const float* x      = (const float*)d_in[0];
    const float* emb_w  = (const float*)d_in[1];
    const float* emb_b  = (const float*)d_in[2];
    const float* qkv_w  = (const float*)d_in[3];
    const float* qkv_b  = (const float*)d_in[4];
    const float* out_w  = (const float*)d_in[5];
    const float* out_b  = (const float*)d_in[6];
    const float* ln1_g  = (const float*)d_in[7];
    const float* ln1_b  = (const float*)d_in[8];
    const float* ln2_g  = (const float*)d_in[9];
    const float* ln2_b  = (const float*)d_in[10];
    const float* ff1_w  = (const float*)d_in[11];
    const float* ff1_b  = (const float*)d_in[12];
    const float* ff2_w  = (const float*)d_in[13];
    const float* ff2_b  = (const float*)d_in[14];
    const float* fn_g   = (const float*)d_in[15];
    const float* fn_b   = (const float*)d_in[16];
    const float* mlp1_w = (const float*)d_in[17];
    const float* mlp1_b = (const float*)d_in[18];
    const float* mlp2_w = (const float*)d_in[19];
    const float* mlp2_b = (const float*)d_in[20];
    const float* mlp3_w = (const float*)d_in[21];
    const float* mlp3_b = (const float*)d_in[22];
    const float* proj_w = (const float*)d_in[23];
    const float* proj_b = (const float*)d_in[24];
    const float* u      = (const float*)d_in[25];
    const float* hbias  = (const float*)d_in[26];

    float* out = (float*)d_out;
    float* out_lam = out + (size_t)B_ * D_ * PRED_;
    float* out_u = out_lam + (size_t)B_ * D_ * D_;

    float *zt, *t, *qkv, *ctx, *y, *mid, *hp;
    cudaGetSymbolAddress((void**)&zt, g_zt);
    cudaGetSymbolAddress((void**)&t, g_t);
    cudaGetSymbolAddress((void**)&qkv, g_qkv);
    cudaGetSymbolAddress((void**)&ctx, g_ctx);
    cudaGetSymbolAddress((void**)&y, g_y);
    cudaGetSymbolAddress((void**)&mid, g_mid);
    cudaGetSymbolAddress((void**)&hp, g_hp);

    cudaFuncSetAttribute(lam_kernel, cudaFuncAttributeMaxDynamicSharedMemorySize, 128 * 129 * 4);
    cudaFuncSetAttribute(attn_kernel, cudaFuncAttributeMaxDynamicSharedMemorySize, ATTN_SMEM);

    const int ROWS = B_ * D_;   // 8192

    // copula + factor MLP
    transpose_x_kernel<<<dim3(L_ / 32, D_ / 32, B_), dim3(32, 8)>>>(x);
    copula_kernel<<<B_ * D_, 1024>>>();
    mlp12_kernel<<<B_, 64>>>(mlp1_w, mlp1_b, mlp2_w, mlp2_b);
    lower_kernel<<<dim3(B_, (D_ * M_) / 256), 256>>>(mlp3_w, mlp3_b);
    lam_kernel<<<B_, 256, 128 * 129 * 4>>>(out_lam);

    // embedding: t = zt @ emb_w^T + emb_b
    gemm_nt_kernel<<<dim3(DM_ / 128, ROWS / 128), 256>>>(zt, emb_w, emb_b, t, ROWS, DM_, L_, 0);

    // transformer layers
    for (int l = 0; l < NL_; ++l) {
        gemm_nt_kernel<<<dim3(3 * DM_ / 128, ROWS / 128), 256>>>(
            t, qkv_w + (size_t)l * 3 * DM_ * DM_, qkv_b + (size_t)l * 3 * DM_,
            qkv, ROWS, 3 * DM_, DM_, 0);
        attn_kernel<<<B_ * H_, 128, ATTN_SMEM>>>();
        gemm_nt_kernel<<<dim3(DM_ / 128, ROWS / 128), 256>>>(
            ctx, out_w + (size_t)l * DM_ * DM_, out_b + (size_t)l * DM_,
            y, ROWS, DM_, DM_, 0);
        resid_ln_kernel<<<ROWS, 128>>>(y, ln1_g + l * DM_, ln1_b + l * DM_, 1);
        gemm_nt_kernel<<<dim3(2 * DM_ / 128, ROWS / 128), 256>>>(
            t, ff1_w + (size_t)l * 2 * DM_ * DM_, ff1_b + (size_t)l * 2 * DM_,
            mid, ROWS, 2 * DM_, DM_, 1);
        gemm_nt_kernel<<<dim3(DM_ / 128, ROWS / 128), 256>>>(
            mid, ff2_w + (size_t)l * DM_ * 2 * DM_, ff2_b + (size_t)l * DM_,
            y, ROWS, DM_, 2 * DM_, 0);
        resid_ln_kernel<<<ROWS, 128>>>(y, ln2_g + l * DM_, ln2_b + l * DM_, 1);
    }

    // final LN (no residual)
    resid_ln_kernel<<<ROWS, 128>>>(y, fn_g, fn_b, 0);

    // head projection + combine
    gemm_nt_kernel<<<dim3(M_ / 128, ROWS / 128), 256>>>(t, proj_w, proj_b, hp, ROWS, M_, DM_, 0);
    head_kernel<<<ROWS, 128>>>(u, hbias, out_lam, out);

    // u passthrough
    cudaMemcpyAsync(out_u, u, (size_t)D_ * M_ * sizeof(float), cudaMemcpyDeviceToDevice);
}

// round 4
// speedup vs baseline: 1.7500x; 1.7500x over previous
#include <cuda_runtime.h>
#include <cuda_bf16.h>
#include <cstdint>
#include <math.h>

#define B_    64
#define L_    1024
#define D_    128
#define M_    128
#define DM_   512
#define NL_   4
#define H_    8
#define DH_   64
#define PRED_ 96

// ================= helpers =================
__device__ __forceinline__ uint32_t smem_to_u32(const void* smem_ptr) {
    uint32_t addr;
    asm("{ .reg .u64 tmp; cvta.to.shared.u64 tmp, %1; cvt.u32.u64 %0, tmp; }"
        : "=r"(addr) : "l"(smem_ptr));
    return addr;
}
__device__ __forceinline__ void ldsm_x4(uint32_t& r0, uint32_t& r1, uint32_t& r2,
                                        uint32_t& r3, uint32_t addr) {
    asm volatile("ldmatrix.sync.aligned.m8n8.x4.shared.b16 {%0,%1,%2,%3}, [%4];"
                 : "=r"(r0), "=r"(r1), "=r"(r2), "=r"(r3) : "r"(addr));
}
__device__ __forceinline__ void mma_bf16(float* d, const uint32_t* a, const uint32_t* b) {
    asm volatile(
        "mma.sync.aligned.m16n8k16.row.col.f32.bf16.bf16.f32 "
        "{%0,%1,%2,%3}, {%4,%5,%6,%7}, {%8,%9}, {%0,%1,%2,%3};"
        : "+f"(d[0]), "+f"(d[1]), "+f"(d[2]), "+f"(d[3])
        : "r"(a[0]), "r"(a[1]), "r"(a[2]), "r"(a[3]), "r"(b[0]), "r"(b[1]));
}

// ---------------- scratch (device globals; no allocation) ----------------
__device__ float g_xt[(size_t)B_ * D_ * L_];       // x transposed [B,D,L]
__device__ float g_zt[(size_t)B_ * D_ * L_];       // z transposed [B,D,L]
__device__ float g_s[B_ * 2 * D_];                 // [B, 2D] mean|std
__device__ float g_h2[B_ * 32];
__device__ float g_lower[(size_t)B_ * D_ * M_];    // [B,D,M]
__device__ float g_t[(size_t)B_ * D_ * DM_];       // backbone state
__device__ float g_qkv[(size_t)B_ * D_ * 3 * DM_];
__device__ float g_ctx[(size_t)B_ * D_ * DM_];
__device__ float g_y[(size_t)B_ * D_ * DM_];       // proj outputs pre-LN
__device__ float g_mid[(size_t)B_ * D_ * 2 * DM_];
__device__ float g_hp[(size_t)B_ * D_ * M_];

// ---------------- transpose x [B,L,D] -> g_xt [B,D,L] ----------------
__global__ void transpose_x_kernel(const float* __restrict__ x) {
    __shared__ float tile[32][33];
    int b = blockIdx.z;
    int l0 = blockIdx.x * 32, d0 = blockIdx.y * 32;
    int lx = threadIdx.x, ly = threadIdx.y;
#pragma unroll
    for (int r = 0; r < 32; r += 8)
        tile[ly + r][lx] = x[((size_t)b * L_ + (l0 + ly + r)) * D_ + (d0 + lx)];
    __syncthreads();
#pragma unroll
    for (int r = 0; r < 32; r += 8)
        g_xt[((size_t)b * D_ + (d0 + ly + r)) * L_ + (l0 + lx)] = tile[lx][ly + r];
}

// ---------------- copula: bitonic rank -> erfinv z, fused mean/std ----------------
__global__ __launch_bounds__(1024) void copula_kernel() {
    __shared__ float vals[L_];
    __shared__ int   idxs[L_];
    __shared__ int   rankof[L_];
    __shared__ float sq[L_];

    int blk = blockIdx.x;            // b*D + d
    int tid = threadIdx.x;
    const float* col = g_xt + (size_t)blk * L_;

    vals[tid] = col[tid];
    idxs[tid] = tid;
    __syncthreads();

    for (int k = 2; k <= L_; k <<= 1) {
        for (int j = k >> 1; j > 0; j >>= 1) {
            int ixj = tid ^ j;
            if (ixj > tid) {
                bool up = ((tid & k) == 0);
                float v1 = vals[tid], v2 = vals[ixj];
                int   i1 = idxs[tid], i2 = idxs[ixj];
                bool gt = (v1 > v2) || (v1 == v2 && i1 > i2);
                if (gt == up) {
                    vals[tid] = v2; vals[ixj] = v1;
                    idxs[tid] = i2; idxs[ixj] = i1;
                }
            }
            __syncthreads();
        }
    }
    rankof[idxs[tid]] = tid;
    __syncthreads();

    int r = rankof[tid];
    float u = ((float)(r + 1) + 0.5f) * (1.0f / (float)L_);
    u = fminf(fmaxf(u, 1e-6f), 1.0f - 1e-6f);
    float zv = erfinvf(2.0f * u - 1.0f) * 1.41421356237309515f;
    g_zt[(size_t)blk * L_ + tid] = zv;

    __syncthreads();
    vals[tid] = zv;
    sq[tid] = zv * zv;
    __syncthreads();
    for (int s = 512; s > 0; s >>= 1) {
        if (tid < s) { vals[tid] += vals[tid + s]; sq[tid] += sq[tid + s]; }
        __syncthreads();
    }
    if (tid == 0) {
        float sum = vals[0], ssq = sq[0];
        float mean = sum * (1.0f / (float)L_);
        float var = (ssq - sum * sum * (1.0f / (float)L_)) * (1.0f / (float)(L_ - 1));
        int b = blk / D_, d = blk % D_;
        g_s[b * 2 * D_ + d] = mean;
        g_s[b * 2 * D_ + D_ + d] = sqrtf(fmaxf(var, 0.0f));
    }
}

// ---------------- s -> relu(mlp1) -> relu(mlp2) -> g_h2 ----------------
__global__ void mlp12_kernel(const float* __restrict__ w1, const float* __restrict__ b1,
                             const float* __restrict__ w2, const float* __restrict__ b2) {
    __shared__ float srow[2 * D_];
    __shared__ float h1[64];
    int b = blockIdx.x, tid = threadIdx.x;   // 64 threads
    for (int i = tid; i < 2 * D_; i += 64) srow[i] = g_s[b * 2 * D_ + i];
    __syncthreads();
    float acc = b1[tid];
    for (int k = 0; k < 2 * D_; ++k) acc += srow[k] * w1[tid * 2 * D_ + k];
    h1[tid] = fmaxf(acc, 0.0f);
    __syncthreads();
    if (tid < 32) {
        float a2 = b2[tid];
        for (int k = 0; k < 64; ++k) a2 += h1[k] * w2[tid * 64 + k];
        g_h2[b * 32 + tid] = fmaxf(a2, 0.0f);
    }
}

// ---------------- lower = h2 @ mlp3_w^T + b  -> [B, D*M] ----------------
__global__ __launch_bounds__(256) void lower_kernel(const float* __restrict__ w3,
                                                    const float* __restrict__ b3) {
    __shared__ float h2s[32];
    __shared__ float wt[256][33];
    int b = blockIdx.x;
    int j0 = blockIdx.y * 256;
    int tid = threadIdx.x;
    if (tid < 32) h2s[tid] = g_h2[b * 32 + tid];
    for (int i = tid; i < 256 * 32; i += 256) {
        int rr = i >> 5, cc = i & 31;
        wt[rr][cc] = w3[(size_t)j0 * 32 + i];
    }
    __syncthreads();
    float acc = b3[j0 + tid];
#pragma unroll
    for (int k = 0; k < 32; ++k) acc += h2s[k] * wt[tid][k];
    g_lower[(size_t)b * (D_ * M_) + j0 + tid] = acc;
}

// ---------------- lam[b] = lower[b] @ lower[b]^T  (writes into d_out) ----------------
__global__ __launch_bounds__(256) void lam_kernel(float* __restrict__ lam_out) {
    extern __shared__ float low[];   // [128][129] padded
    int b = blockIdx.x, tid = threadIdx.x;
    for (int i = tid; i < D_ * M_; i += 256) {
        int rr = i >> 7, cc = i & 127;
        low[rr * 129 + cc] = g_lower[(size_t)b * (D_ * M_) + i];
    }
    __syncthreads();
    for (int e = tid; e < D_ * D_; e += 256) {
        int i = e >> 7, j = e & 127;
        const float* ri = &low[i * 129];
        const float* rj = &low[j * 129];
        float acc = 0.0f;
#pragma unroll 8
        for (int m = 0; m < M_; ++m) acc += ri[m] * rj[m];
        lam_out[(size_t)b * D_ * D_ + e] = acc;
    }
}

// ================= mma.sync bf16x3 NT GEMM: C[8192,N] = A[8192,K] @ B[N,K]^T + bias ========
// 128x128 tile per CTA, 8 warps (4x2), warp tile 32x64. K staged in chunks of 64.
// fp32 -> hi/lo bf16 split in the staging pass; acc = Ahi*Bhi + Ahi*Blo + Alo*Bhi (fp32).
#define GDYN (64 * 1024 + 1024)
__global__ __launch_bounds__(256, 2) void gemm_mma_kernel(
    const float* __restrict__ A, const float* __restrict__ Bm,
    const float* __restrict__ bias, float* __restrict__ C,
    int Ndim, int Kdim, int relu)
{
    extern __shared__ char dsm_raw[];
    uint32_t dsm_u0 = smem_to_u32(dsm_raw);
    uint32_t base_u = (dsm_u0 + 1023u) & ~1023u;      // 1024-align for swizzle
    char* dsm = dsm_raw + (base_u - dsm_u0);

    int tid = threadIdx.x;
    int wid = tid >> 5, lane = tid & 31;
    int n0 = blockIdx.x * 128, m0 = blockIdx.y * 128;
    int wm = (wid & 3) * 32;     // warp M offset in tile
    int wn = (wid >> 2) * 64;    // warp N offset in tile

    // smem layout (bf16, rows of 64 elems = 128B, SW128 XOR swizzle):
    const uint32_t SAHI = 0, SALO = 16384, SBHI = 32768, SBLO = 49152;

    float acc[2][8][4];
#pragma unroll
    for (int a = 0; a < 2; ++a)
#pragma unroll
        for (int b = 0; b < 8; ++b)
#pragma unroll
            for (int c = 0; c < 4; ++c) acc[a][b][c] = 0.0f;

    int nchunks = Kdim >> 6;
    for (int ch = 0; ch < nchunks; ++ch) {
        int k0 = ch << 6;
        __syncthreads();   // previous chunk's reads done before overwrite
        // stage fp32 -> hi/lo bf16 into swizzled smem
        for (int i = tid; i < 2048; i += 256) {
            int isB = i >> 10;
            int s = i & 1023;
            int r = s >> 3, seg = s & 7;
            const float* src = (isB ? Bm + (size_t)(n0 + r) * Kdim
                                    : A + (size_t)(m0 + r) * Kdim) + k0 + seg * 8;
            float4 f0 = *(const float4*)src;
            float4 f1 = *(const float4*)(src + 4);
            float f[8] = {f0.x, f0.y, f0.z, f0.w, f1.x, f1.y, f1.z, f1.w};
            union { __nv_bfloat16 h[8]; uint4 u; } hv, lv;
#pragma unroll
            for (int t = 0; t < 8; ++t) {
                __nv_bfloat16 h = __float2bfloat16(f[t]);
                hv.h[t] = h;
                lv.h[t] = __float2bfloat16(f[t] - __bfloat162float(h));
            }
            uint32_t off = (uint32_t)(r * 128 + seg * 16);
            uint32_t sw = off ^ ((off >> 3) & 0x70);
            uint32_t bh = isB ? SBHI : SAHI;
            *(uint4*)(dsm + bh + sw) = hv.u;            // hi
            *(uint4*)(dsm + bh + 16384 + sw) = lv.u;    // lo
        }
        __syncthreads();

#pragma unroll
        for (int s = 0; s < 4; ++s) {       // four k16 steps inside the chunk
            uint32_t ahi[2][4], alo[2][4];
#pragma unroll
            for (int mt = 0; mt < 2; ++mt) {
                uint32_t off = (uint32_t)((wm + mt * 16 + (lane & 15)) * 128
                                          + s * 32 + ((lane >> 4) << 4));
                uint32_t sw = off ^ ((off >> 3) & 0x70);
                ldsm_x4(ahi[mt][0], ahi[mt][1], ahi[mt][2], ahi[mt][3], base_u + SAHI + sw);
                ldsm_x4(alo[mt][0], alo[mt][1], alo[mt][2], alo[mt][3], base_u + SALO + sw);
            }
#pragma unroll
            for (int p = 0; p < 4; ++p) {   // 16 N-columns per iteration
                uint32_t off = (uint32_t)((wn + p * 16 + ((lane >> 3) & 1) * 8 + (lane & 7)) * 128
                                          + s * 32 + ((lane >> 4) << 4));
                uint32_t sw = off ^ ((off >> 3) & 0x70);
                uint32_t bh[4], bl[4];
                ldsm_x4(bh[0], bh[1], bh[2], bh[3], base_u + SBHI + sw);
                ldsm_x4(bl[0], bl[1], bl[2], bl[3], base_u + SBLO + sw);
                uint32_t bh0[2] = {bh[0], bh[2]}, bh1[2] = {bh[1], bh[3]};
                uint32_t bl0[2] = {bl[0], bl[2]}, bl1[2] = {bl[1], bl[3]};
#pragma unroll
                for (int mt = 0; mt < 2; ++mt) {
                    mma_bf16(acc[mt][2 * p],     ahi[mt], bh0);
                    mma_bf16(acc[mt][2 * p + 1], ahi[mt], bh1);
                    mma_bf16(acc[mt][2 * p],     ahi[mt], bl0);
                    mma_bf16(acc[mt][2 * p + 1], ahi[mt], bl1);
                    mma_bf16(acc[mt][2 * p],     alo[mt], bh0);
                    mma_bf16(acc[mt][2 * p + 1], alo[mt], bh1);
                }
            }
        }
    }

    // epilogue: direct register -> global with bias/relu
    int r4 = lane >> 2, c2 = (lane & 3) * 2;
#pragma unroll
    for (int mt = 0; mt < 2; ++mt) {
        int row0 = m0 + wm + mt * 16 + r4;
#pragma unroll
        for (int nb = 0; nb < 8; ++nb) {
            int col = n0 + wn + nb * 8 + c2;
            float bx = bias[col], by = bias[col + 1];
            float2 v0 = {acc[mt][nb][0] + bx, acc[mt][nb][1] + by};
            float2 v1 = {acc[mt][nb][2] + bx, acc[mt][nb][3] + by};
            if (relu) {
                v0.x = fmaxf(v0.x, 0.f); v0.y = fmaxf(v0.y, 0.f);
                v1.x = fmaxf(v1.x, 0.f); v1.y = fmaxf(v1.y, 0.f);
            }
            *(float2*)&C[(size_t)row0 * Ndim + col] = v0;
            *(float2*)&C[(size_t)(row0 + 8) * Ndim + col] = v1;
        }
    }
}

// ---------------- fused attention per (b,h): softmax(qk^T/8) v ----------------
#define ATTN_SMEM ((2 * 128 * 64 + 128 * 129) * 4)
__global__ __launch_bounds__(128) void attn_kernel() {
    extern __shared__ float sm[];
    float* ks = sm;                    // [128][64]
    float* vs = sm + 128 * 64;         // [128][64]
    float* sc = sm + 2 * 128 * 64;     // [128][129]

    int bh = blockIdx.x;
    int b = bh >> 3, h = bh & 7;
    int tid = threadIdx.x;
    const float* qkvb = g_qkv + (size_t)b * D_ * 3 * DM_;

    const float* krow = qkvb + (size_t)tid * 3 * DM_ + DM_ + h * DH_;
    const float* vrow = qkvb + (size_t)tid * 3 * DM_ + 2 * DM_ + h * DH_;
#pragma unroll
    for (int c = 0; c < DH_; c += 4) {
        *(float4*)&ks[tid * DH_ + c] = *(const float4*)(krow + c);
        *(float4*)&vs[tid * DH_ + c] = *(const float4*)(vrow + c);
    }
    float qv[DH_];
    const float* qrow = qkvb + (size_t)tid * 3 * DM_ + h * DH_;
#pragma unroll
    for (int c = 0; c < DH_; c += 4) {
        float4 q4 = *(const float4*)(qrow + c);
        qv[c] = q4.x; qv[c + 1] = q4.y; qv[c + 2] = q4.z; qv[c + 3] = q4.w;
    }
    __syncthreads();

    float* myrow = &sc[tid * 129];
    float mx = -1e30f;
    for (int j = 0; j < 128; ++j) {
        const float* kj = &ks[j * DH_];
        float a = 0.0f;
#pragma unroll
        for (int c = 0; c < DH_; ++c) a += qv[c] * kj[c];
        a *= 0.125f;
        myrow[j] = a;
        mx = fmaxf(mx, a);
    }
    float ssum = 0.0f;
    for (int j = 0; j < 128; ++j) {
        float e = __expf(myrow[j] - mx);
        myrow[j] = e;
        ssum += e;
    }
    float inv = 1.0f / ssum;

    float acc2[DH_];
#pragma unroll
    for (int c = 0; c < DH_; ++c) acc2[c] = 0.0f;
    for (int j = 0; j < 128; ++j) {
        float p = myrow[j] * inv;
        const float* vj = &vs[j * DH_];
#pragma unroll
        for (int c = 0; c < DH_; ++c) acc2[c] += p * vj[c];
    }
    float* orow = g_ctx + ((size_t)b * D_ + tid) * DM_ + h * DH_;
#pragma unroll
    for (int c = 0; c < DH_; c += 4) {
        float4 o4 = {acc2[c], acc2[c + 1], acc2[c + 2], acc2[c + 3]};
        *(float4*)(orow + c) = o4;
    }
}

// ---------------- residual + layernorm (in-place on g_t) ----------------
__global__ __launch_bounds__(128) void resid_ln_kernel(const float* __restrict__ y,
                                                       const float* __restrict__ gam,
                                                       const float* __restrict__ bet,
                                                       int has_res) {
    int row = blockIdx.x, tid = threadIdx.x;
    float* trow = g_t + (size_t)row * DM_;
    const float* yrow = y + (size_t)row * DM_;
    float v[4];
    float s = 0.0f, sq = 0.0f;
#pragma unroll
    for (int r = 0; r < 4; ++r) {
        int c = tid + r * 128;
        float val = trow[c];
        if (has_res) val += yrow[c];
        v[r] = val; s += val; sq += val * val;
    }
    __shared__ float rs[4], rq[4];
    unsigned lane = tid & 31, wid = tid >> 5;
#pragma unroll
    for (int off = 16; off; off >>= 1) {
        s += __shfl_down_sync(0xffffffffu, s, off);
        sq += __shfl_down_sync(0xffffffffu, sq, off);
    }
    if (lane == 0) { rs[wid] = s; rq[wid] = sq; }
    __syncthreads();
    float S = rs[0] + rs[1] + rs[2] + rs[3];
    float SQ = rq[0] + rq[1] + rq[2] + rq[3];
    float mean = S * (1.0f / (float)DM_);
    float var = SQ * (1.0f / (float)DM_) - mean * mean;
    float rstd = rsqrtf(var + 1e-5f);
#pragma unroll
    for (int r = 0; r < 4; ++r) {
        int c = tid + r * 128;
        trow[c] = (v[r] - mean) * rstd * gam[c] + bet[c];
    }
}

// ---------------- head: y = diag(hp @ (lam@u^T)) broadcast to pred_len ----------------
__global__ __launch_bounds__(128) void head_kernel(const float* __restrict__ u,
                                                   const float* __restrict__ head_bias,
                                                   const float* __restrict__ lam,
                                                   float* __restrict__ out_y) {
    __shared__ float hps[M_];
    __shared__ float red[4];
    __shared__ float ybc;
    int blk = blockIdx.x;              // b*D + i
    int b = blk >> 7, i = blk & 127;
    int tid = threadIdx.x;             // = m
    hps[tid] = g_hp[(size_t)blk * M_ + tid];
    __syncthreads();
    const float* lamb = lam + (size_t)b * D_ * D_;
    float acc = 0.0f;
    for (int k = 0; k < D_; ++k) acc += hps[k] * lamb[(size_t)k * D_ + tid];
    float p = acc * u[(size_t)i * M_ + tid];
    unsigned lane = tid & 31, wid = tid >> 5;
#pragma unroll
    for (int off = 16; off; off >>= 1) p += __shfl_down_sync(0xffffffffu, p, off);
    if (lane == 0) red[wid] = p;
    __syncthreads();
    if (tid == 0) ybc = red[0] + red[1] + red[2] + red[3] + head_bias[i];
    __syncthreads();
    float yv = ybc;
    if (tid < PRED_) out_y[(size_t)blk * PRED_ + tid] = yv;
}

// ---------------- host launcher ----------------
extern "C" void kernel_launch(void* const* d_in, const int* in_sizes, int n_in,
                              void* d_out, int out_size) {
    const float* x      = (const float*)d_in[0];
    const float* emb_w  = (const float*)d_in[1];
    const float* emb_b  = (const float*)d_in[2];
    const float* qkv_w  = (const float*)d_in[3];
    const float* qkv_b  = (const float*)d_in[4];
    const float* out_w  = (const float*)d_in[5];
    const float* out_b  = (const float*)d_in[6];
    const float* ln1_g  = (const float*)d_in[7];
    const float* ln1_b  = (const float*)d_in[8];
    const float* ln2_g  = (const float*)d_in[9];
    const float* ln2_b  = (const float*)d_in[10];
    const float* ff1_w  = (const float*)d_in[11];
    const float* ff1_b  = (const float*)d_in[12];
    const float* ff2_w  = (const float*)d_in[13];
    const float* ff2_b  = (const float*)d_in[14];
    const float* fn_g   = (const float*)d_in[15];
    const float* fn_b   = (const float*)d_in[16];
    const float* mlp1_w = (const float*)d_in[17];
    const float* mlp1_b = (const float*)d_in[18];
    const float* mlp2_w = (const float*)d_in[19];
    const float* mlp2_b = (const float*)d_in[20];
    const float* mlp3_w = (const float*)d_in[21];
    const float* mlp3_b = (const float*)d_in[22];
    const float* proj_w = (const float*)d_in[23];
    const float* proj_b = (const float*)d_in[24];
    const float* u      = (const float*)d_in[25];
    const float* hbias  = (const float*)d_in[26];

    float* out = (float*)d_out;
    float* out_lam = out + (size_t)B_ * D_ * PRED_;
    float* out_u = out_lam + (size_t)B_ * D_ * D_;

    float *zt, *t, *qkv, *ctx, *y, *mid, *hp;
    cudaGetSymbolAddress((void**)&zt, g_zt);
    cudaGetSymbolAddress((void**)&t, g_t);
    cudaGetSymbolAddress((void**)&qkv, g_qkv);
    cudaGetSymbolAddress((void**)&ctx, g_ctx);
    cudaGetSymbolAddress((void**)&y, g_y);
    cudaGetSymbolAddress((void**)&mid, g_mid);
    cudaGetSymbolAddress((void**)&hp, g_hp);

    cudaFuncSetAttribute(lam_kernel, cudaFuncAttributeMaxDynamicSharedMemorySize, 128 * 129 * 4);
    cudaFuncSetAttribute(attn_kernel, cudaFuncAttributeMaxDynamicSharedMemorySize, ATTN_SMEM);
    cudaFuncSetAttribute(gemm_mma_kernel, cudaFuncAttributeMaxDynamicSharedMemorySize, GDYN);

    const int ROWS = B_ * D_;   // 8192

    // copula + factor MLP
    transpose_x_kernel<<<dim3(L_ / 32, D_ / 32, B_), dim3(32, 8)>>>(x);
    copula_kernel<<<B_ * D_, 1024>>>();
    mlp12_kernel<<<B_, 64>>>(mlp1_w, mlp1_b, mlp2_w, mlp2_b);
    lower_kernel<<<dim3(B_, (D_ * M_) / 256), 256>>>(mlp3_w, mlp3_b);
    lam_kernel<<<B_, 256, 128 * 129 * 4>>>(out_lam);

    // embedding: t = zt @ emb_w^T + emb_b
    gemm_mma_kernel<<<dim3(DM_ / 128, ROWS / 128), 256, GDYN>>>(zt, emb_w, emb_b, t, DM_, L_, 0);

    // transformer layers
    for (int l = 0; l < NL_; ++l) {
        gemm_mma_kernel<<<dim3(3 * DM_ / 128, ROWS / 128), 256, GDYN>>>(
            t, qkv_w + (size_t)l * 3 * DM_ * DM_, qkv_b + (size_t)l * 3 * DM_,
            qkv, 3 * DM_, DM_, 0);
        attn_kernel<<<B_ * H_, 128, ATTN_SMEM>>>();
        gemm_mma_kernel<<<dim3(DM_ / 128, ROWS / 128), 256, GDYN>>>(
            ctx, out_w + (size_t)l * DM_ * DM_, out_b + (size_t)l * DM_,
            y, DM_, DM_, 0);
        resid_ln_kernel<<<ROWS, 128>>>(y, ln1_g + l * DM_, ln1_b + l * DM_, 1);
        gemm_mma_kernel<<<dim3(2 * DM_ / 128, ROWS / 128), 256, GDYN>>>(
            t, ff1_w + (size_t)l * 2 * DM_ * DM_, ff1_b + (size_t)l * 2 * DM_,
            mid, 2 * DM_, DM_, 1);
        gemm_mma_kernel<<<dim3(DM_ / 128, ROWS / 128), 256, GDYN>>>(
            mid, ff2_w + (size_t)l * DM_ * 2 * DM_, ff2_b + (size_t)l * DM_,
            y, DM_, 2 * DM_, 0);
        resid_ln_kernel<<<ROWS, 128>>>(y, ln2_g + l * DM_, ln2_b + l * DM_, 1);
    }

    // final LN (no residual)
    resid_ln_kernel<<<ROWS, 128>>>(y, fn_g, fn_b, 0);

    // head projection + combine
    gemm_mma_kernel<<<dim3(M_ / 128, ROWS / 128), 256, GDYN>>>(t, proj_w, proj_b, hp, M_, DM_, 0);
    head_kernel<<<ROWS, 128>>>(u, hbias, out_lam, out);

    // u passthrough
    cudaMemcpyAsync(out_u, u, (size_t)D_ * M_ * sizeof(float), cudaMemcpyDeviceToDevice);
}

// round 5
// speedup vs baseline: 1.8687x; 1.0678x over previous
#include <cuda_runtime.h>
#include <cuda_bf16.h>
#include <cstdint>
#include <math.h>

#define B_    64
#define L_    1024
#define D_    128
#define M_    128
#define DM_   512
#define NL_   4
#define H_    8
#define DH_   64
#define PRED_ 96

// ================= helpers =================
__device__ __forceinline__ uint32_t smem_to_u32(const void* smem_ptr) {
    uint32_t addr;
    asm("{ .reg .u64 tmp; cvta.to.shared.u64 tmp, %1; cvt.u32.u64 %0, tmp; }"
        : "=r"(addr) : "l"(smem_ptr));
    return addr;
}
__device__ __forceinline__ void ldsm_x4(uint32_t& r0, uint32_t& r1, uint32_t& r2,
                                        uint32_t& r3, uint32_t addr) {
    asm volatile("ldmatrix.sync.aligned.m8n8.x4.shared.b16 {%0,%1,%2,%3}, [%4];"
                 : "=r"(r0), "=r"(r1), "=r"(r2), "=r"(r3) : "r"(addr));
}
__device__ __forceinline__ void mma_bf16(float* d, const uint32_t* a, const uint32_t* b) {
    asm volatile(
        "mma.sync.aligned.m16n8k16.row.col.f32.bf16.bf16.f32 "
        "{%0,%1,%2,%3}, {%4,%5,%6,%7}, {%8,%9}, {%0,%1,%2,%3};"
        : "+f"(d[0]), "+f"(d[1]), "+f"(d[2]), "+f"(d[3])
        : "r"(a[0]), "r"(a[1]), "r"(a[2]), "r"(a[3]), "r"(b[0]), "r"(b[1]));
}
__device__ __forceinline__ void cp_async16(uint32_t saddr, const void* gptr) {
    asm volatile("cp.async.cg.shared.global [%0], [%1], 16;" :: "r"(saddr), "l"(gptr));
}
__device__ __forceinline__ void cp_commit() {
    asm volatile("cp.async.commit_group;" ::: "memory");
}
template<int N> __device__ __forceinline__ void cp_wait() {
    asm volatile("cp.async.wait_group %0;" :: "n"(N) : "memory");
}

// ---------------- scratch (device globals; no allocation) ----------------
__device__ float g_xt[(size_t)B_ * D_ * L_];          // x transposed [B,D,L]
__device__ float g_s[B_ * 2 * D_];
__device__ float g_h2[B_ * 32];
__device__ float g_lower[(size_t)B_ * D_ * M_];
__device__ float g_t[(size_t)B_ * D_ * DM_];          // backbone state fp32
__device__ float g_qkv[(size_t)B_ * D_ * 3 * DM_];
__device__ float g_y[(size_t)B_ * D_ * DM_];
__device__ float g_hp[(size_t)B_ * D_ * M_];

// bf16 hi/lo activation buffers
__device__ __nv_bfloat16 g_zhi[(size_t)B_ * D_ * L_];
__device__ __nv_bfloat16 g_zlo[(size_t)B_ * D_ * L_];
__device__ __nv_bfloat16 g_thi[(size_t)B_ * D_ * DM_];
__device__ __nv_bfloat16 g_tlo[(size_t)B_ * D_ * DM_];
__device__ __nv_bfloat16 g_ctxhi[(size_t)B_ * D_ * DM_];
__device__ __nv_bfloat16 g_ctxlo[(size_t)B_ * D_ * DM_];
__device__ __nv_bfloat16 g_midhi[(size_t)B_ * D_ * 2 * DM_];
__device__ __nv_bfloat16 g_midlo[(size_t)B_ * D_ * 2 * DM_];

// bf16 hi/lo weight buffers (packed, see OFF_*)
#define OFF_EMB  0
#define OFF_QKV  524288
#define OFF_OUT  3670016
#define OFF_FF1  4718592
#define OFF_FF2  6815744
#define OFF_PROJ 8912896
#define W_TOTAL  8978432
__device__ __nv_bfloat16 g_whi[W_TOTAL];
__device__ __nv_bfloat16 g_wlo[W_TOTAL];

// ---------------- fp32 -> (hi, lo) bf16 pair conversion ----------------
__global__ void cvt_pair_kernel(const float* __restrict__ src,
                                __nv_bfloat16* __restrict__ hi,
                                __nv_bfloat16* __restrict__ lo, int n4) {
    int i = blockIdx.x * blockDim.x + threadIdx.x;
    if (i >= n4) return;
    float4 f = ((const float4*)src)[i];
    __nv_bfloat16 h0 = __float2bfloat16(f.x), h1 = __float2bfloat16(f.y);
    __nv_bfloat16 h2 = __float2bfloat16(f.z), h3 = __float2bfloat16(f.w);
    __nv_bfloat162* hp = (__nv_bfloat162*)hi;
    __nv_bfloat162* lp = (__nv_bfloat162*)lo;
    hp[2 * i] = __nv_bfloat162(h0, h1);
    hp[2 * i + 1] = __nv_bfloat162(h2, h3);
    lp[2 * i] = __nv_bfloat162(__float2bfloat16(f.x - __bfloat162float(h0)),
                               __float2bfloat16(f.y - __bfloat162float(h1)));
    lp[2 * i + 1] = __nv_bfloat162(__float2bfloat16(f.z - __bfloat162float(h2)),
                                   __float2bfloat16(f.w - __bfloat162float(h3)));
}

// ---------------- transpose x [B,L,D] -> g_xt [B,D,L] ----------------
__global__ void transpose_x_kernel(const float* __restrict__ x) {
    __shared__ float tile[32][33];
    int b = blockIdx.z;
    int l0 = blockIdx.x * 32, d0 = blockIdx.y * 32;
    int lx = threadIdx.x, ly = threadIdx.y;
#pragma unroll
    for (int r = 0; r < 32; r += 8)
        tile[ly + r][lx] = x[((size_t)b * L_ + (l0 + ly + r)) * D_ + (d0 + lx)];
    __syncthreads();
#pragma unroll
    for (int r = 0; r < 32; r += 8)
        g_xt[((size_t)b * D_ + (d0 + ly + r)) * L_ + (l0 + lx)] = tile[lx][ly + r];
}

// ---------------- copula: bitonic rank -> erfinv z (emitted hi/lo), fused mean/std ----------------
__global__ __launch_bounds__(1024) void copula_kernel() {
    __shared__ float vals[L_];
    __shared__ int   idxs[L_];
    __shared__ int   rankof[L_];
    __shared__ float sq[L_];

    int blk = blockIdx.x;            // b*D + d
    int tid = threadIdx.x;
    const float* col = g_xt + (size_t)blk * L_;

    vals[tid] = col[tid];
    idxs[tid] = tid;
    __syncthreads();

    for (int k = 2; k <= L_; k <<= 1) {
        for (int j = k >> 1; j > 0; j >>= 1) {
            int ixj = tid ^ j;
            if (ixj > tid) {
                bool up = ((tid & k) == 0);
                float v1 = vals[tid], v2 = vals[ixj];
                int   i1 = idxs[tid], i2 = idxs[ixj];
                bool gt = (v1 > v2) || (v1 == v2 && i1 > i2);
                if (gt == up) {
                    vals[tid] = v2; vals[ixj] = v1;
                    idxs[tid] = i2; idxs[ixj] = i1;
                }
            }
            __syncthreads();
        }
    }
    rankof[idxs[tid]] = tid;
    __syncthreads();

    int r = rankof[tid];
    float u = ((float)(r + 1) + 0.5f) * (1.0f / (float)L_);
    u = fminf(fmaxf(u, 1e-6f), 1.0f - 1e-6f);
    float zv = erfinvf(2.0f * u - 1.0f) * 1.41421356237309515f;
    __nv_bfloat16 zh = __float2bfloat16(zv);
    g_zhi[(size_t)blk * L_ + tid] = zh;
    g_zlo[(size_t)blk * L_ + tid] = __float2bfloat16(zv - __bfloat162float(zh));

    __syncthreads();
    vals[tid] = zv;
    sq[tid] = zv * zv;
    __syncthreads();
    for (int s = 512; s > 0; s >>= 1) {
        if (tid < s) { vals[tid] += vals[tid + s]; sq[tid] += sq[tid + s]; }
        __syncthreads();
    }
    if (tid == 0) {
        float sum = vals[0], ssq = sq[0];
        float mean = sum * (1.0f / (float)L_);
        float var = (ssq - sum * sum * (1.0f / (float)L_)) * (1.0f / (float)(L_ - 1));
        int b = blk / D_, d = blk % D_;
        g_s[b * 2 * D_ + d] = mean;
        g_s[b * 2 * D_ + D_ + d] = sqrtf(fmaxf(var, 0.0f));
    }
}

// ---------------- s -> relu(mlp1) -> relu(mlp2) -> g_h2 ----------------
__global__ void mlp12_kernel(const float* __restrict__ w1, const float* __restrict__ b1,
                             const float* __restrict__ w2, const float* __restrict__ b2) {
    __shared__ float srow[2 * D_];
    __shared__ float h1[64];
    int b = blockIdx.x, tid = threadIdx.x;
    for (int i = tid; i < 2 * D_; i += 64) srow[i] = g_s[b * 2 * D_ + i];
    __syncthreads();
    float acc = b1[tid];
    for (int k = 0; k < 2 * D_; ++k) acc += srow[k] * w1[tid * 2 * D_ + k];
    h1[tid] = fmaxf(acc, 0.0f);
    __syncthreads();
    if (tid < 32) {
        float a2 = b2[tid];
        for (int k = 0; k < 64; ++k) a2 += h1[k] * w2[tid * 64 + k];
        g_h2[b * 32 + tid] = fmaxf(a2, 0.0f);
    }
}

// ---------------- lower = h2 @ mlp3_w^T + b ----------------
__global__ __launch_bounds__(256) void lower_kernel(const float* __restrict__ w3,
                                                    const float* __restrict__ b3) {
    __shared__ float h2s[32];
    __shared__ float wt[256][33];
    int b = blockIdx.x;
    int j0 = blockIdx.y * 256;
    int tid = threadIdx.x;
    if (tid < 32) h2s[tid] = g_h2[b * 32 + tid];
    for (int i = tid; i < 256 * 32; i += 256) {
        int rr = i >> 5, cc = i & 31;
        wt[rr][cc] = w3[(size_t)j0 * 32 + i];
    }
    __syncthreads();
    float acc = b3[j0 + tid];
#pragma unroll
    for (int k = 0; k < 32; ++k) acc += h2s[k] * wt[tid][k];
    g_lower[(size_t)b * (D_ * M_) + j0 + tid] = acc;
}

// ---------------- lam[b] = lower[b] @ lower[b]^T  (into d_out) ----------------
__global__ __launch_bounds__(256) void lam_kernel(float* __restrict__ lam_out) {
    extern __shared__ float low[];   // [128][129]
    int b = blockIdx.x, tid = threadIdx.x;
    for (int i = tid; i < D_ * M_; i += 256) {
        int rr = i >> 7, cc = i & 127;
        low[rr * 129 + cc] = g_lower[(size_t)b * (D_ * M_) + i];
    }
    __syncthreads();
    for (int e = tid; e < D_ * D_; e += 256) {
        int i = e >> 7, j = e & 127;
        const float* ri = &low[i * 129];
        const float* rj = &low[j * 129];
        float acc = 0.0f;
#pragma unroll 8
        for (int m = 0; m < M_; ++m) acc += ri[m] * rj[m];
        lam_out[(size_t)b * D_ * D_ + e] = acc;
    }
}

// ================= pipelined mma.sync bf16x3 NT GEMM =================
// C[8192,N] = A @ B^T + bias.  A,B pre-split to bf16 hi/lo arrays, K-major.
// 128x128 CTA tile, 8 warps (4x2), K chunks of 32, 3-stage cp.async pipeline.
// stage layout (bf16 rows of 32 elems = 64B, SW64 swizzle): AHI 0, ALO 8K, BHI 16K, BLO 24K.
#define STAGES 3
#define STG_BYTES 32768
#define GDYN (STAGES * STG_BYTES + 1024)
__global__ __launch_bounds__(256, 2) void gemm_mma_kernel(
    const __nv_bfloat16* __restrict__ Ahi, const __nv_bfloat16* __restrict__ Alo,
    const __nv_bfloat16* __restrict__ Bhi, const __nv_bfloat16* __restrict__ Blo,
    const float* __restrict__ bias, float* __restrict__ C,
    __nv_bfloat16* __restrict__ Chi, __nv_bfloat16* __restrict__ Clo,
    int Ndim, int Kdim, int relu, int writeC)
{
    extern __shared__ char dsm_raw[];
    uint32_t dsm_u0 = smem_to_u32(dsm_raw);
    uint32_t base_u = (dsm_u0 + 1023u) & ~1023u;
    int tid = threadIdx.x;
    int wid = tid >> 5, lane = tid & 31;
    int n0 = blockIdx.x * 128, m0 = blockIdx.y * 128;
    int wm = (wid & 3) * 32;
    int wn = (wid >> 2) * 64;

    float acc[2][8][4];
#pragma unroll
    for (int a = 0; a < 2; ++a)
#pragma unroll
        for (int b = 0; b < 8; ++b)
#pragma unroll
            for (int c = 0; c < 4; ++c) acc[a][b][c] = 0.0f;

    int nch = Kdim >> 5;

    // stage fill: 2048 x 16B cp.async (4 tensors x 128 rows x 4 segs)
    auto stage_fill = [&](int ch, int stg) {
        int k0 = ch << 5;
        uint32_t sb = base_u + stg * STG_BYTES;
#pragma unroll
        for (int t = 0; t < 8; ++t) {
            int idx = tid + t * 256;
            int tensor = idx >> 9;
            int r = (idx >> 2) & 127;
            int cs = idx & 3;
            const __nv_bfloat16* g;
            if (tensor == 0) g = Ahi; else if (tensor == 1) g = Alo;
            else if (tensor == 2) g = Bhi; else g = Blo;
            int rr = ((tensor < 2) ? m0 : n0) + r;
            g += (size_t)rr * Kdim + k0 + cs * 8;
            uint32_t off = (uint32_t)(r * 64 + cs * 16);
            uint32_t sw = off ^ ((off >> 3) & 0x30);
            cp_async16(sb + tensor * 8192 + sw, g);
        }
        cp_commit();
    };

    stage_fill(0, 0);
    stage_fill(1, 1);

    for (int ch = 0; ch < nch; ++ch) {
        if (ch == nch - 1) cp_wait<0>(); else cp_wait<1>();
        __syncthreads();
        if (ch + 2 < nch) stage_fill(ch + 2, (ch + 2) % STAGES);

        uint32_t sb = base_u + (ch % STAGES) * STG_BYTES;
#pragma unroll
        for (int s = 0; s < 2; ++s) {
            uint32_t ahf[2][4], alf[2][4];
#pragma unroll
            for (int mt = 0; mt < 2; ++mt) {
                uint32_t off = (uint32_t)((wm + mt * 16 + (lane & 15)) * 64
                                          + s * 32 + ((lane >> 4) << 4));
                uint32_t sw = off ^ ((off >> 3) & 0x30);
                ldsm_x4(ahf[mt][0], ahf[mt][1], ahf[mt][2], ahf[mt][3], sb + sw);
                ldsm_x4(alf[mt][0], alf[mt][1], alf[mt][2], alf[mt][3], sb + 8192 + sw);
            }
#pragma unroll
            for (int p = 0; p < 4; ++p) {
                uint32_t off = (uint32_t)((wn + p * 16 + ((lane >> 3) & 1) * 8 + (lane & 7)) * 64
                                          + s * 32 + ((lane >> 4) << 4));
                uint32_t sw = off ^ ((off >> 3) & 0x30);
                uint32_t bh[4], bl[4];
                ldsm_x4(bh[0], bh[1], bh[2], bh[3], sb + 16384 + sw);
                ldsm_x4(bl[0], bl[1], bl[2], bl[3], sb + 24576 + sw);
                uint32_t bh0[2] = {bh[0], bh[2]}, bh1[2] = {bh[1], bh[3]};
                uint32_t bl0[2] = {bl[0], bl[2]}, bl1[2] = {bl[1], bl[3]};
#pragma unroll
                for (int mt = 0; mt < 2; ++mt) {
                    mma_bf16(acc[mt][2 * p],     ahf[mt], bh0);
                    mma_bf16(acc[mt][2 * p + 1], ahf[mt], bh1);
                    mma_bf16(acc[mt][2 * p],     ahf[mt], bl0);
                    mma_bf16(acc[mt][2 * p + 1], ahf[mt], bl1);
                    mma_bf16(acc[mt][2 * p],     alf[mt], bh0);
                    mma_bf16(acc[mt][2 * p + 1], alf[mt], bh1);
                }
            }
        }
    }

    // epilogue: bias/relu, optional fp32 C, optional bf16 hi/lo C
    int r4 = lane >> 2, c2 = (lane & 3) * 2;
#pragma unroll
    for (int mt = 0; mt < 2; ++mt) {
        int row0 = m0 + wm + mt * 16 + r4;
#pragma unroll
        for (int nb = 0; nb < 8; ++nb) {
            int col = n0 + wn + nb * 8 + c2;
            float bx = bias[col], by = bias[col + 1];
            float2 v0 = {acc[mt][nb][0] + bx, acc[mt][nb][1] + by};
            float2 v1 = {acc[mt][nb][2] + bx, acc[mt][nb][3] + by};
            if (relu) {
                v0.x = fmaxf(v0.x, 0.f); v0.y = fmaxf(v0.y, 0.f);
                v1.x = fmaxf(v1.x, 0.f); v1.y = fmaxf(v1.y, 0.f);
            }
            size_t i0 = (size_t)row0 * Ndim + col;
            size_t i1 = (size_t)(row0 + 8) * Ndim + col;
            if (writeC) {
                *(float2*)&C[i0] = v0;
                *(float2*)&C[i1] = v1;
            }
            if (Chi) {
                __nv_bfloat162 h0 = __floats2bfloat162_rn(v0.x, v0.y);
                __nv_bfloat162 h1 = __floats2bfloat162_rn(v1.x, v1.y);
                *(__nv_bfloat162*)&Chi[i0] = h0;
                *(__nv_bfloat162*)&Chi[i1] = h1;
                *(__nv_bfloat162*)&Clo[i0] = __floats2bfloat162_rn(
                    v0.x - __bfloat162float(h0.x), v0.y - __bfloat162float(h0.y));
                *(__nv_bfloat162*)&Clo[i1] = __floats2bfloat162_rn(
                    v1.x - __bfloat162float(h1.x), v1.y - __bfloat162float(h1.y));
            }
        }
    }
}

// ---------------- fused attention per (b,h): softmax(qk^T/8) v -> ctx hi/lo ----------------
#define ATTN_SMEM ((2 * 128 * 64 + 128 * 129) * 4)
__global__ __launch_bounds__(128) void attn_kernel() {
    extern __shared__ float sm[];
    float* ks = sm;
    float* vs = sm + 128 * 64;
    float* sc = sm + 2 * 128 * 64;

    int bh = blockIdx.x;
    int b = bh >> 3, h = bh & 7;
    int tid = threadIdx.x;
    const float* qkvb = g_qkv + (size_t)b * D_ * 3 * DM_;

    const float* krow = qkvb + (size_t)tid * 3 * DM_ + DM_ + h * DH_;
    const float* vrow = qkvb + (size_t)tid * 3 * DM_ + 2 * DM_ + h * DH_;
#pragma unroll
    for (int c = 0; c < DH_; c += 4) {
        *(float4*)&ks[tid * DH_ + c] = *(const float4*)(krow + c);
        *(float4*)&vs[tid * DH_ + c] = *(const float4*)(vrow + c);
    }
    float qv[DH_];
    const float* qrow = qkvb + (size_t)tid * 3 * DM_ + h * DH_;
#pragma unroll
    for (int c = 0; c < DH_; c += 4) {
        float4 q4 = *(const float4*)(qrow + c);
        qv[c] = q4.x; qv[c + 1] = q4.y; qv[c + 2] = q4.z; qv[c + 3] = q4.w;
    }
    __syncthreads();

    float* myrow = &sc[tid * 129];
    float mx = -1e30f;
    for (int j = 0; j < 128; ++j) {
        const float* kj = &ks[j * DH_];
        float a = 0.0f;
#pragma unroll
        for (int c = 0; c < DH_; ++c) a += qv[c] * kj[c];
        a *= 0.125f;
        myrow[j] = a;
        mx = fmaxf(mx, a);
    }
    float ssum = 0.0f;
    for (int j = 0; j < 128; ++j) {
        float e = __expf(myrow[j] - mx);
        myrow[j] = e;
        ssum += e;
    }
    float inv = 1.0f / ssum;

    float acc2[DH_];
#pragma unroll
    for (int c = 0; c < DH_; ++c) acc2[c] = 0.0f;
    for (int j = 0; j < 128; ++j) {
        float p = myrow[j] * inv;
        const float* vj = &vs[j * DH_];
#pragma unroll
        for (int c = 0; c < DH_; ++c) acc2[c] += p * vj[c];
    }
    size_t obase = ((size_t)b * D_ + tid) * DM_ + h * DH_;
#pragma unroll
    for (int c = 0; c < DH_; c += 2) {
        __nv_bfloat162 hx = __floats2bfloat162_rn(acc2[c], acc2[c + 1]);
        *(__nv_bfloat162*)&g_ctxhi[obase + c] = hx;
        *(__nv_bfloat162*)&g_ctxlo[obase + c] = __floats2bfloat162_rn(
            acc2[c] - __bfloat162float(hx.x), acc2[c + 1] - __bfloat162float(hx.y));
    }
}

// ---------------- residual + layernorm (in-place on g_t, emits hi/lo) ----------------
__global__ __launch_bounds__(128) void resid_ln_kernel(const float* __restrict__ y,
                                                       const float* __restrict__ gam,
                                                       const float* __restrict__ bet,
                                                       int has_res) {
    int row = blockIdx.x, tid = threadIdx.x;
    float* trow = g_t + (size_t)row * DM_;
    const float* yrow = y + (size_t)row * DM_;
    float v[4];
    float s = 0.0f, sq = 0.0f;
#pragma unroll
    for (int r = 0; r < 4; ++r) {
        int c = tid + r * 128;
        float val = trow[c];
        if (has_res) val += yrow[c];
        v[r] = val; s += val; sq += val * val;
    }
    __shared__ float rs[4], rq[4];
    unsigned lane = tid & 31, wid = tid >> 5;
#pragma unroll
    for (int off = 16; off; off >>= 1) {
        s += __shfl_down_sync(0xffffffffu, s, off);
        sq += __shfl_down_sync(0xffffffffu, sq, off);
    }
    if (lane == 0) { rs[wid] = s; rq[wid] = sq; }
    __syncthreads();
    float S = rs[0] + rs[1] + rs[2] + rs[3];
    float SQ = rq[0] + rq[1] + rq[2] + rq[3];
    float mean = S * (1.0f / (float)DM_);
    float var = SQ * (1.0f / (float)DM_) - mean * mean;
    float rstd = rsqrtf(var + 1e-5f);
#pragma unroll
    for (int r = 0; r < 4; ++r) {
        int c = tid + r * 128;
        float o = (v[r] - mean) * rstd * gam[c] + bet[c];
        trow[c] = o;
        __nv_bfloat16 hx = __float2bfloat16(o);
        g_thi[(size_t)row * DM_ + c] = hx;
        g_tlo[(size_t)row * DM_ + c] = __float2bfloat16(o - __bfloat162float(hx));
    }
}

// ---------------- head: y = diag(hp @ (lam@u^T)) broadcast to pred_len ----------------
__global__ __launch_bounds__(128) void head_kernel(const float* __restrict__ u,
                                                   const float* __restrict__ head_bias,
                                                   const float* __restrict__ lam,
                                                   float* __restrict__ out_y) {
    __shared__ float hps[M_];
    __shared__ float red[4];
    __shared__ float ybc;
    int blk = blockIdx.x;
    int b = blk >> 7, i = blk & 127;
    int tid = threadIdx.x;
    hps[tid] = g_hp[(size_t)blk * M_ + tid];
    __syncthreads();
    const float* lamb = lam + (size_t)b * D_ * D_;
    float acc = 0.0f;
    for (int k = 0; k < D_; ++k) acc += hps[k] * lamb[(size_t)k * D_ + tid];
    float p = acc * u[(size_t)i * M_ + tid];
    unsigned lane = tid & 31, wid = tid >> 5;
#pragma unroll
    for (int off = 16; off; off >>= 1) p += __shfl_down_sync(0xffffffffu, p, off);
    if (lane == 0) red[wid] = p;
    __syncthreads();
    if (tid == 0) ybc = red[0] + red[1] + red[2] + red[3] + head_bias[i];
    __syncthreads();
    float yv = ybc;
    if (tid < PRED_) out_y[(size_t)blk * PRED_ + tid] = yv;
}

// ---------------- host launcher ----------------
extern "C" void kernel_launch(void* const* d_in, const int* in_sizes, int n_in,
                              void* d_out, int out_size) {
    const float* x      = (const float*)d_in[0];
    const float* emb_w  = (const float*)d_in[1];
    const float* emb_b  = (const float*)d_in[2];
    const float* qkv_w  = (const float*)d_in[3];
    const float* qkv_b  = (const float*)d_in[4];
    const float* out_w  = (const float*)d_in[5];
    const float* out_b  = (const float*)d_in[6];
    const float* ln1_g  = (const float*)d_in[7];
    const float* ln1_b  = (const float*)d_in[8];
    const float* ln2_g  = (const float*)d_in[9];
    const float* ln2_b  = (const float*)d_in[10];
    const float* ff1_w  = (const float*)d_in[11];
    const float* ff1_b  = (const float*)d_in[12];
    const float* ff2_w  = (const float*)d_in[13];
    const float* ff2_b  = (const float*)d_in[14];
    const float* fn_g   = (const float*)d_in[15];
    const float* fn_b   = (const float*)d_in[16];
    const float* mlp1_w = (const float*)d_in[17];
    const float* mlp1_b = (const float*)d_in[18];
    const float* mlp2_w = (const float*)d_in[19];
    const float* mlp2_b = (const float*)d_in[20];
    const float* mlp3_w = (const float*)d_in[21];
    const float* mlp3_b = (const float*)d_in[22];
    const float* proj_w = (const float*)d_in[23];
    const float* proj_b = (const float*)d_in[24];
    const float* u      = (const float*)d_in[25];
    const float* hbias  = (const float*)d_in[26];

    float* out = (float*)d_out;
    float* out_lam = out + (size_t)B_ * D_ * PRED_;
    float* out_u = out_lam + (size_t)B_ * D_ * D_;

    float *t, *qkv, *y, *hp;
    __nv_bfloat16 *zhi, *zlo, *thi, *tlo, *chi, *clo, *mhi, *mlo, *whi, *wlo;
    cudaGetSymbolAddress((void**)&t, g_t);
    cudaGetSymbolAddress((void**)&qkv, g_qkv);
    cudaGetSymbolAddress((void**)&y, g_y);
    cudaGetSymbolAddress((void**)&hp, g_hp);
    cudaGetSymbolAddress((void**)&zhi, g_zhi);
    cudaGetSymbolAddress((void**)&zlo, g_zlo);
    cudaGetSymbolAddress((void**)&thi, g_thi);
    cudaGetSymbolAddress((void**)&tlo, g_tlo);
    cudaGetSymbolAddress((void**)&chi, g_ctxhi);
    cudaGetSymbolAddress((void**)&clo, g_ctxlo);
    cudaGetSymbolAddress((void**)&mhi, g_midhi);
    cudaGetSymbolAddress((void**)&mlo, g_midlo);
    cudaGetSymbolAddress((void**)&whi, g_whi);
    cudaGetSymbolAddress((void**)&wlo, g_wlo);

    cudaFuncSetAttribute(lam_kernel, cudaFuncAttributeMaxDynamicSharedMemorySize, 128 * 129 * 4);
    cudaFuncSetAttribute(attn_kernel, cudaFuncAttributeMaxDynamicSharedMemorySize, ATTN_SMEM);
    cudaFuncSetAttribute(gemm_mma_kernel, cudaFuncAttributeMaxDynamicSharedMemorySize, GDYN);

    const int ROWS = B_ * D_;   // 8192

    // weight conversions (once per launch; graph replays them, cost ~20us)
    auto cvt = [&](const float* src, size_t off, int n) {
        cvt_pair_kernel<<<(n / 4 + 255) / 256, 256>>>(src, whi + off, wlo + off, n / 4);
    };
    cvt(emb_w, OFF_EMB, 524288);
    cvt(qkv_w, OFF_QKV, 3145728);
    cvt(out_w, OFF_OUT, 1048576);
    cvt(ff1_w, OFF_FF1, 2097152);
    cvt(ff2_w, OFF_FF2, 2097152);
    cvt(proj_w, OFF_PROJ, 65536);

    // copula + factor MLP
    transpose_x_kernel<<<dim3(L_ / 32, D_ / 32, B_), dim3(32, 8)>>>(x);
    copula_kernel<<<B_ * D_, 1024>>>();
    mlp12_kernel<<<B_, 64>>>(mlp1_w, mlp1_b, mlp2_w, mlp2_b);
    lower_kernel<<<dim3(B_, (D_ * M_) / 256), 256>>>(mlp3_w, mlp3_b);
    lam_kernel<<<B_, 256, 128 * 129 * 4>>>(out_lam);

    // embedding: t = z @ emb_w^T + emb_b   (emit t fp32 + hi/lo)
    gemm_mma_kernel<<<dim3(DM_ / 128, ROWS / 128), 256, GDYN>>>(
        zhi, zlo, whi + OFF_EMB, wlo + OFF_EMB, emb_b, t, thi, tlo, DM_, L_, 0, 1);

    for (int l = 0; l < NL_; ++l) {
        gemm_mma_kernel<<<dim3(3 * DM_ / 128, ROWS / 128), 256, GDYN>>>(
            thi, tlo, whi + OFF_QKV + (size_t)l * 3 * DM_ * DM_,
            wlo + OFF_QKV + (size_t)l * 3 * DM_ * DM_, qkv_b + (size_t)l * 3 * DM_,
            qkv, nullptr, nullptr, 3 * DM_, DM_, 0, 1);
        attn_kernel<<<B_ * H_, 128, ATTN_SMEM>>>();
        gemm_mma_kernel<<<dim3(DM_ / 128, ROWS / 128), 256, GDYN>>>(
            chi, clo, whi + OFF_OUT + (size_t)l * DM_ * DM_,
            wlo + OFF_OUT + (size_t)l * DM_ * DM_, out_b + (size_t)l * DM_,
            y, nullptr, nullptr, DM_, DM_, 0, 1);
        resid_ln_kernel<<<ROWS, 128>>>(y, ln1_g + l * DM_, ln1_b + l * DM_, 1);
        gemm_mma_kernel<<<dim3(2 * DM_ / 128, ROWS / 128), 256, GDYN>>>(
            thi, tlo, whi + OFF_FF1 + (size_t)l * 2 * DM_ * DM_,
            wlo + OFF_FF1 + (size_t)l * 2 * DM_ * DM_, ff1_b + (size_t)l * 2 * DM_,
            nullptr, mhi, mlo, 2 * DM_, DM_, 1, 0);
        gemm_mma_kernel<<<dim3(DM_ / 128, ROWS / 128), 256, GDYN>>>(
            mhi, mlo, whi + OFF_FF2 + (size_t)l * DM_ * 2 * DM_,
            wlo + OFF_FF2 + (size_t)l * DM_ * 2 * DM_, ff2_b + (size_t)l * DM_,
            y, nullptr, nullptr, DM_, 2 * DM_, 0, 1);
        resid_ln_kernel<<<ROWS, 128>>>(y, ln2_g + l * DM_, ln2_b + l * DM_, 1);
    }

    // final LN (no residual) -> t + hi/lo
    resid_ln_kernel<<<ROWS, 128>>>(y, fn_g, fn_b, 0);

    // head projection + combine
    gemm_mma_kernel<<<dim3(M_ / 128, ROWS / 128), 256, GDYN>>>(
        thi, tlo, whi + OFF_PROJ, wlo + OFF_PROJ, proj_b, hp, nullptr, nullptr, M_, DM_, 0, 1);
    head_kernel<<<ROWS, 128>>>(u, hbias, out_lam, out);

    // u passthrough
    cudaMemcpyAsync(out_u, u, (size_t)D_ * M_ * sizeof(float), cudaMemcpyDeviceToDevice);
}

// round 6
// speedup vs baseline: 2.3325x; 1.2482x over previous
#include <cuda_runtime.h>
#include <cuda_fp16.h>
#include <cstdint>
#include <math.h>

#define B_    64
#define L_    1024
#define D_    128
#define M_    128
#define DM_   512
#define NL_   4
#define H_    8
#define DH_   64
#define PRED_ 96

// ================= helpers =================
__device__ __forceinline__ uint32_t smem_to_u32(const void* smem_ptr) {
    uint32_t addr;
    asm("{ .reg .u64 tmp; cvta.to.shared.u64 tmp, %1; cvt.u32.u64 %0, tmp; }"
        : "=r"(addr) : "l"(smem_ptr));
    return addr;
}
__device__ __forceinline__ void ldsm_x4(uint32_t& r0, uint32_t& r1, uint32_t& r2,
                                        uint32_t& r3, uint32_t addr) {
    asm volatile("ldmatrix.sync.aligned.m8n8.x4.shared.b16 {%0,%1,%2,%3}, [%4];"
                 : "=r"(r0), "=r"(r1), "=r"(r2), "=r"(r3) : "r"(addr));
}
__device__ __forceinline__ void mma_f16(float* d, const uint32_t* a, const uint32_t* b) {
    asm volatile(
        "mma.sync.aligned.m16n8k16.row.col.f32.f16.f16.f32 "
        "{%0,%1,%2,%3}, {%4,%5,%6,%7}, {%8,%9}, {%0,%1,%2,%3};"
        : "+f"(d[0]), "+f"(d[1]), "+f"(d[2]), "+f"(d[3])
        : "r"(a[0]), "r"(a[1]), "r"(a[2]), "r"(a[3]), "r"(b[0]), "r"(b[1]));
}
__device__ __forceinline__ void cp_async16(uint32_t saddr, const void* gptr) {
    asm volatile("cp.async.cg.shared.global [%0], [%1], 16;" :: "r"(saddr), "l"(gptr));
}
__device__ __forceinline__ void cp_commit() {
    asm volatile("cp.async.commit_group;" ::: "memory");
}
template<int N> __device__ __forceinline__ void cp_wait() {
    asm volatile("cp.async.wait_group %0;" :: "n"(N) : "memory");
}

// ---------------- scratch (device globals; no allocation) ----------------
__device__ float g_xt[(size_t)B_ * D_ * L_];
__device__ float g_s[B_ * 2 * D_];
__device__ float g_h2[B_ * 32];
__device__ float g_lower[(size_t)B_ * D_ * M_];
__device__ float g_t[(size_t)B_ * D_ * DM_];          // backbone state fp32
__device__ float g_qkv[(size_t)B_ * D_ * 3 * DM_];
__device__ float g_y[(size_t)B_ * D_ * DM_];
__device__ float g_hp[(size_t)B_ * D_ * M_];

// fp16 single activation buffers
__device__ __half g_zh[(size_t)B_ * D_ * L_];
__device__ __half g_th[(size_t)B_ * D_ * DM_];
__device__ __half g_ctxh[(size_t)B_ * D_ * DM_];
__device__ __half g_midh[(size_t)B_ * D_ * 2 * DM_];

// fp16 hi/lo weight buffers (packed)
#define OFF_EMB  0
#define OFF_QKV  524288
#define OFF_OUT  3670016
#define OFF_FF1  4718592
#define OFF_FF2  6815744
#define OFF_PROJ 8912896
#define W_TOTAL  8978432
__device__ __half g_whi[W_TOTAL];
__device__ __half g_wlo[W_TOTAL];

// ---------------- fp32 -> (hi, lo) fp16 pair conversion ----------------
__global__ void cvt_pair_kernel(const float* __restrict__ src,
                                __half* __restrict__ hi,
                                __half* __restrict__ lo, int n4) {
    int i = blockIdx.x * blockDim.x + threadIdx.x;
    if (i >= n4) return;
    float4 f = ((const float4*)src)[i];
    __half h0 = __float2half(f.x), h1 = __float2half(f.y);
    __half h2 = __float2half(f.z), h3 = __float2half(f.w);
    __half2* hp = (__half2*)hi;
    __half2* lp = (__half2*)lo;
    hp[2 * i] = __half2(h0, h1);
    hp[2 * i + 1] = __half2(h2, h3);
    lp[2 * i] = __half2(__float2half(f.x - __half2float(h0)),
                        __float2half(f.y - __half2float(h1)));
    lp[2 * i + 1] = __half2(__float2half(f.z - __half2float(h2)),
                            __float2half(f.w - __half2float(h3)));
}

// ---------------- transpose x [B,L,D] -> g_xt [B,D,L] ----------------
__global__ void transpose_x_kernel(const float* __restrict__ x) {
    __shared__ float tile[32][33];
    int b = blockIdx.z;
    int l0 = blockIdx.x * 32, d0 = blockIdx.y * 32;
    int lx = threadIdx.x, ly = threadIdx.y;
#pragma unroll
    for (int r = 0; r < 32; r += 8)
        tile[ly + r][lx] = x[((size_t)b * L_ + (l0 + ly + r)) * D_ + (d0 + lx)];
    __syncthreads();
#pragma unroll
    for (int r = 0; r < 32; r += 8)
        g_xt[((size_t)b * D_ + (d0 + ly + r)) * L_ + (l0 + lx)] = tile[lx][ly + r];
}

// ---------------- copula: bitonic rank -> erfinv z (fp16), fused mean/std ----------------
__global__ __launch_bounds__(1024) void copula_kernel() {
    __shared__ float vals[L_];
    __shared__ int   idxs[L_];
    __shared__ int   rankof[L_];
    __shared__ float sq[L_];

    int blk = blockIdx.x;
    int tid = threadIdx.x;
    const float* col = g_xt + (size_t)blk * L_;

    vals[tid] = col[tid];
    idxs[tid] = tid;
    __syncthreads();

    for (int k = 2; k <= L_; k <<= 1) {
        for (int j = k >> 1; j > 0; j >>= 1) {
            int ixj = tid ^ j;
            if (ixj > tid) {
                bool up = ((tid & k) == 0);
                float v1 = vals[tid], v2 = vals[ixj];
                int   i1 = idxs[tid], i2 = idxs[ixj];
                bool gt = (v1 > v2) || (v1 == v2 && i1 > i2);
                if (gt == up) {
                    vals[tid] = v2; vals[ixj] = v1;
                    idxs[tid] = i2; idxs[ixj] = i1;
                }
            }
            __syncthreads();
        }
    }
    rankof[idxs[tid]] = tid;
    __syncthreads();

    int r = rankof[tid];
    float u = ((float)(r + 1) + 0.5f) * (1.0f / (float)L_);
    u = fminf(fmaxf(u, 1e-6f), 1.0f - 1e-6f);
    float zv = erfinvf(2.0f * u - 1.0f) * 1.41421356237309515f;
    g_zh[(size_t)blk * L_ + tid] = __float2half(zv);

    __syncthreads();
    vals[tid] = zv;
    sq[tid] = zv * zv;
    __syncthreads();
    for (int s = 512; s > 0; s >>= 1) {
        if (tid < s) { vals[tid] += vals[tid + s]; sq[tid] += sq[tid + s]; }
        __syncthreads();
    }
    if (tid == 0) {
        float sum = vals[0], ssq = sq[0];
        float mean = sum * (1.0f / (float)L_);
        float var = (ssq - sum * sum * (1.0f / (float)L_)) * (1.0f / (float)(L_ - 1));
        int b = blk / D_, d = blk % D_;
        g_s[b * 2 * D_ + d] = mean;
        g_s[b * 2 * D_ + D_ + d] = sqrtf(fmaxf(var, 0.0f));
    }
}

// ---------------- s -> relu(mlp1) -> relu(mlp2) -> g_h2 ----------------
__global__ void mlp12_kernel(const float* __restrict__ w1, const float* __restrict__ b1,
                             const float* __restrict__ w2, const float* __restrict__ b2) {
    __shared__ float srow[2 * D_];
    __shared__ float h1[64];
    int b = blockIdx.x, tid = threadIdx.x;
    for (int i = tid; i < 2 * D_; i += 64) srow[i] = g_s[b * 2 * D_ + i];
    __syncthreads();
    float acc = b1[tid];
    for (int k = 0; k < 2 * D_; ++k) acc += srow[k] * w1[tid * 2 * D_ + k];
    h1[tid] = fmaxf(acc, 0.0f);
    __syncthreads();
    if (tid < 32) {
        float a2 = b2[tid];
        for (int k = 0; k < 64; ++k) a2 += h1[k] * w2[tid * 64 + k];
        g_h2[b * 32 + tid] = fmaxf(a2, 0.0f);
    }
}

// ---------------- lower = h2 @ mlp3_w^T + b ----------------
__global__ __launch_bounds__(256) void lower_kernel(const float* __restrict__ w3,
                                                    const float* __restrict__ b3) {
    __shared__ float h2s[32];
    __shared__ float wt[256][33];
    int b = blockIdx.x;
    int j0 = blockIdx.y * 256;
    int tid = threadIdx.x;
    if (tid < 32) h2s[tid] = g_h2[b * 32 + tid];
    for (int i = tid; i < 256 * 32; i += 256) {
        int rr = i >> 5, cc = i & 31;
        wt[rr][cc] = w3[(size_t)j0 * 32 + i];
    }
    __syncthreads();
    float acc = b3[j0 + tid];
#pragma unroll
    for (int k = 0; k < 32; ++k) acc += h2s[k] * wt[tid][k];
    g_lower[(size_t)b * (D_ * M_) + j0 + tid] = acc;
}

// ---------------- lam[b] = lower[b] @ lower[b]^T  (into d_out) ----------------
__global__ __launch_bounds__(256) void lam_kernel(float* __restrict__ lam_out) {
    extern __shared__ float low[];   // [128][129]
    int b = blockIdx.x, tid = threadIdx.x;
    for (int i = tid; i < D_ * M_; i += 256) {
        int rr = i >> 7, cc = i & 127;
        low[rr * 129 + cc] = g_lower[(size_t)b * (D_ * M_) + i];
    }
    __syncthreads();
    for (int e = tid; e < D_ * D_; e += 256) {
        int i = e >> 7, j = e & 127;
        const float* ri = &low[i * 129];
        const float* rj = &low[j * 129];
        float acc = 0.0f;
#pragma unroll 8
        for (int m = 0; m < M_; ++m) acc += ri[m] * rj[m];
        lam_out[(size_t)b * D_ * D_ + e] = acc;
    }
}

// ================= pipelined mma.sync fp16x2 NT GEMM =================
// C[8192,N] = A @ W^T + bias. A: single fp16 activations. W: fp16 hi/lo (2-term).
// 128x128 CTA tile, 8 warps (4x2), K chunks of 32, 4-stage cp.async pipeline.
// stage layout (rows of 32 halves = 64B, SW64 swizzle): A 0, WHI 8K, WLO 16K.
#define STAGES 4
#define STG_BYTES 24576
#define GDYN (STAGES * STG_BYTES + 1024)
__global__ __launch_bounds__(256, 2) void gemm_mma_kernel(
    const __half* __restrict__ Ah,
    const __half* __restrict__ Whi, const __half* __restrict__ Wlo,
    const float* __restrict__ bias, float* __restrict__ C,
    __half* __restrict__ Ch,
    int Ndim, int Kdim, int relu, int writeC)
{
    extern __shared__ char dsm_raw[];
    uint32_t dsm_u0 = smem_to_u32(dsm_raw);
    uint32_t base_u = (dsm_u0 + 1023u) & ~1023u;
    int tid = threadIdx.x;
    int wid = tid >> 5, lane = tid & 31;
    int n0 = blockIdx.x * 128, m0 = blockIdx.y * 128;
    int wm = (wid & 3) * 32;
    int wn = (wid >> 2) * 64;

    float acc[2][8][4];
#pragma unroll
    for (int a = 0; a < 2; ++a)
#pragma unroll
        for (int b = 0; b < 8; ++b)
#pragma unroll
            for (int c = 0; c < 4; ++c) acc[a][b][c] = 0.0f;

    int nch = Kdim >> 5;

    // stage fill: 1536 x 16B cp.async (3 tensors x 128 rows x 4 segs)
    auto stage_fill = [&](int ch, int stg) {
        int k0 = ch << 5;
        uint32_t sb = base_u + stg * STG_BYTES;
#pragma unroll
        for (int t = 0; t < 6; ++t) {
            int idx = tid + t * 256;
            int tensor = idx >> 9;
            int r = (idx >> 2) & 127;
            int cs = idx & 3;
            const __half* g;
            if (tensor == 0) g = Ah; else if (tensor == 1) g = Whi; else g = Wlo;
            int rr = ((tensor == 0) ? m0 : n0) + r;
            g += (size_t)rr * Kdim + k0 + cs * 8;
            uint32_t off = (uint32_t)(r * 64 + cs * 16);
            uint32_t sw = off ^ ((off >> 3) & 0x30);
            cp_async16(sb + tensor * 8192 + sw, g);
        }
        cp_commit();
    };

    stage_fill(0, 0);
    stage_fill(1, 1);
    stage_fill(2, 2);

    for (int ch = 0; ch < nch; ++ch) {
        int rem = nch - ch;
        if (rem >= 3) cp_wait<2>();
        else if (rem == 2) cp_wait<1>();
        else cp_wait<0>();
        __syncthreads();
        if (ch + 3 < nch) stage_fill(ch + 3, (ch + 3) % STAGES);

        uint32_t sb = base_u + (ch % STAGES) * STG_BYTES;
#pragma unroll
        for (int s = 0; s < 2; ++s) {
            uint32_t af[2][4];
#pragma unroll
            for (int mt = 0; mt < 2; ++mt) {
                uint32_t off = (uint32_t)((wm + mt * 16 + (lane & 15)) * 64
                                          + s * 32 + ((lane >> 4) << 4));
                uint32_t sw = off ^ ((off >> 3) & 0x30);
                ldsm_x4(af[mt][0], af[mt][1], af[mt][2], af[mt][3], sb + sw);
            }
#pragma unroll
            for (int p = 0; p < 4; ++p) {
                uint32_t off = (uint32_t)((wn + p * 16 + ((lane >> 3) & 1) * 8 + (lane & 7)) * 64
                                          + s * 32 + ((lane >> 4) << 4));
                uint32_t sw = off ^ ((off >> 3) & 0x30);
                uint32_t bh[4], bl[4];
                ldsm_x4(bh[0], bh[1], bh[2], bh[3], sb + 8192 + sw);
                ldsm_x4(bl[0], bl[1], bl[2], bl[3], sb + 16384 + sw);
                uint32_t bh0[2] = {bh[0], bh[2]}, bh1[2] = {bh[1], bh[3]};
                uint32_t bl0[2] = {bl[0], bl[2]}, bl1[2] = {bl[1], bl[3]};
#pragma unroll
                for (int mt = 0; mt < 2; ++mt) {
                    mma_f16(acc[mt][2 * p],     af[mt], bh0);
                    mma_f16(acc[mt][2 * p + 1], af[mt], bh1);
                    mma_f16(acc[mt][2 * p],     af[mt], bl0);
                    mma_f16(acc[mt][2 * p + 1], af[mt], bl1);
                }
            }
        }
    }

    // epilogue: bias/relu, optional fp32 C, optional fp16 C
    int r4 = lane >> 2, c2 = (lane & 3) * 2;
#pragma unroll
    for (int mt = 0; mt < 2; ++mt) {
        int row0 = m0 + wm + mt * 16 + r4;
#pragma unroll
        for (int nb = 0; nb < 8; ++nb) {
            int col = n0 + wn + nb * 8 + c2;
            float bx = bias[col], by = bias[col + 1];
            float2 v0 = {acc[mt][nb][0] + bx, acc[mt][nb][1] + by};
            float2 v1 = {acc[mt][nb][2] + bx, acc[mt][nb][3] + by};
            if (relu) {
                v0.x = fmaxf(v0.x, 0.f); v0.y = fmaxf(v0.y, 0.f);
                v1.x = fmaxf(v1.x, 0.f); v1.y = fmaxf(v1.y, 0.f);
            }
            size_t i0 = (size_t)row0 * Ndim + col;
            size_t i1 = (size_t)(row0 + 8) * Ndim + col;
            if (writeC) {
                *(float2*)&C[i0] = v0;
                *(float2*)&C[i1] = v1;
            }
            if (Ch) {
                *(__half2*)&Ch[i0] = __half2(__float2half(v0.x), __float2half(v0.y));
                *(__half2*)&Ch[i1] = __half2(__float2half(v1.x), __float2half(v1.y));
            }
        }
    }
}

// ---------------- fused attention per (b,h): softmax(qk^T/8) v -> ctx fp16 ----------------
#define ATTN_SMEM ((2 * 128 * 64 + 128 * 129) * 4)
__global__ __launch_bounds__(128) void attn_kernel() {
    extern __shared__ float sm[];
    float* ks = sm;
    float* vs = sm + 128 * 64;
    float* sc = sm + 2 * 128 * 64;

    int bh = blockIdx.x;
    int b = bh >> 3, h = bh & 7;
    int tid = threadIdx.x;
    const float* qkvb = g_qkv + (size_t)b * D_ * 3 * DM_;

    const float* krow = qkvb + (size_t)tid * 3 * DM_ + DM_ + h * DH_;
    const float* vrow = qkvb + (size_t)tid * 3 * DM_ + 2 * DM_ + h * DH_;
#pragma unroll
    for (int c = 0; c < DH_; c += 4) {
        *(float4*)&ks[tid * DH_ + c] = *(const float4*)(krow + c);
        *(float4*)&vs[tid * DH_ + c] = *(const float4*)(vrow + c);
    }
    float qv[DH_];
    const float* qrow = qkvb + (size_t)tid * 3 * DM_ + h * DH_;
#pragma unroll
    for (int c = 0; c < DH_; c += 4) {
        float4 q4 = *(const float4*)(qrow + c);
        qv[c] = q4.x; qv[c + 1] = q4.y; qv[c + 2] = q4.z; qv[c + 3] = q4.w;
    }
    __syncthreads();

    float* myrow = &sc[tid * 129];
    float mx = -1e30f;
    for (int j = 0; j < 128; ++j) {
        const float* kj = &ks[j * DH_];
        float a = 0.0f;
#pragma unroll
        for (int c = 0; c < DH_; ++c) a += qv[c] * kj[c];
        a *= 0.125f;
        myrow[j] = a;
        mx = fmaxf(mx, a);
    }
    float ssum = 0.0f;
    for (int j = 0; j < 128; ++j) {
        float e = __expf(myrow[j] - mx);
        myrow[j] = e;
        ssum += e;
    }
    float inv = 1.0f / ssum;

    float acc2[DH_];
#pragma unroll
    for (int c = 0; c < DH_; ++c) acc2[c] = 0.0f;
    for (int j = 0; j < 128; ++j) {
        float p = myrow[j] * inv;
        const float* vj = &vs[j * DH_];
#pragma unroll
        for (int c = 0; c < DH_; ++c) acc2[c] += p * vj[c];
    }
    size_t obase = ((size_t)b * D_ + tid) * DM_ + h * DH_;
#pragma unroll
    for (int c = 0; c < DH_; c += 2) {
        *(__half2*)&g_ctxh[obase + c] =
            __half2(__float2half(acc2[c]), __float2half(acc2[c + 1]));
    }
}

// ---------------- residual + layernorm (in-place on g_t, emits fp16) ----------------
__global__ __launch_bounds__(128) void resid_ln_kernel(const float* __restrict__ y,
                                                       const float* __restrict__ gam,
                                                       const float* __restrict__ bet,
                                                       int has_res) {
    int row = blockIdx.x, tid = threadIdx.x;
    float* trow = g_t + (size_t)row * DM_;
    const float* yrow = y + (size_t)row * DM_;
    float v[4];
    float s = 0.0f, sq = 0.0f;
#pragma unroll
    for (int r = 0; r < 4; ++r) {
        int c = tid + r * 128;
        float val = trow[c];
        if (has_res) val += yrow[c];
        v[r] = val; s += val; sq += val * val;
    }
    __shared__ float rs[4], rq[4];
    unsigned lane = tid & 31, wid = tid >> 5;
#pragma unroll
    for (int off = 16; off; off >>= 1) {
        s += __shfl_down_sync(0xffffffffu, s, off);
        sq += __shfl_down_sync(0xffffffffu, sq, off);
    }
    if (lane == 0) { rs[wid] = s; rq[wid] = sq; }
    __syncthreads();
    float S = rs[0] + rs[1] + rs[2] + rs[3];
    float SQ = rq[0] + rq[1] + rq[2] + rq[3];
    float mean = S * (1.0f / (float)DM_);
    float var = SQ * (1.0f / (float)DM_) - mean * mean;
    float rstd = rsqrtf(var + 1e-5f);
#pragma unroll
    for (int r = 0; r < 4; ++r) {
        int c = tid + r * 128;
        float o = (v[r] - mean) * rstd * gam[c] + bet[c];
        trow[c] = o;
        g_th[(size_t)row * DM_ + c] = __float2half(o);
    }
}

// ---------------- head: y = diag(hp @ (lam@u^T)) broadcast to pred_len ----------------
__global__ __launch_bounds__(128) void head_kernel(const float* __restrict__ u,
                                                   const float* __restrict__ head_bias,
                                                   const float* __restrict__ lam,
                                                   float* __restrict__ out_y) {
    __shared__ float hps[M_];
    __shared__ float red[4];
    __shared__ float ybc;
    int blk = blockIdx.x;
    int b = blk >> 7, i = blk & 127;
    int tid = threadIdx.x;
    hps[tid] = g_hp[(size_t)blk * M_ + tid];
    __syncthreads();
    const float* lamb = lam + (size_t)b * D_ * D_;
    float acc = 0.0f;
    for (int k = 0; k < D_; ++k) acc += hps[k] * lamb[(size_t)k * D_ + tid];
    float p = acc * u[(size_t)i * M_ + tid];
    unsigned lane = tid & 31, wid = tid >> 5;
#pragma unroll
    for (int off = 16; off; off >>= 1) p += __shfl_down_sync(0xffffffffu, p, off);
    if (lane == 0) red[wid] = p;
    __syncthreads();
    if (tid == 0) ybc = red[0] + red[1] + red[2] + red[3] + head_bias[i];
    __syncthreads();
    float yv = ybc;
    if (tid < PRED_) out_y[(size_t)blk * PRED_ + tid] = yv;
}

// ---------------- host launcher ----------------
extern "C" void kernel_launch(void* const* d_in, const int* in_sizes, int n_in,
                              void* d_out, int out_size) {
    const float* x      = (const float*)d_in[0];
    const float* emb_w  = (const float*)d_in[1];
    const float* emb_b  = (const float*)d_in[2];
    const float* qkv_w  = (const float*)d_in[3];
    const float* qkv_b  = (const float*)d_in[4];
    const float* out_w  = (const float*)d_in[5];
    const float* out_b  = (const float*)d_in[6];
    const float* ln1_g  = (const float*)d_in[7];
    const float* ln1_b  = (const float*)d_in[8];
    const float* ln2_g  = (const float*)d_in[9];
    const float* ln2_b  = (const float*)d_in[10];
    const float* ff1_w  = (const float*)d_in[11];
    const float* ff1_b  = (const float*)d_in[12];
    const float* ff2_w  = (const float*)d_in[13];
    const float* ff2_b  = (const float*)d_in[14];
    const float* fn_g   = (const float*)d_in[15];
    const float* fn_b   = (const float*)d_in[16];
    const float* mlp1_w = (const float*)d_in[17];
    const float* mlp1_b = (const float*)d_in[18];
    const float* mlp2_w = (const float*)d_in[19];
    const float* mlp2_b = (const float*)d_in[20];
    const float* mlp3_w = (const float*)d_in[21];
    const float* mlp3_b = (const float*)d_in[22];
    const float* proj_w = (const float*)d_in[23];
    const float* proj_b = (const float*)d_in[24];
    const float* u      = (const float*)d_in[25];
    const float* hbias  = (const float*)d_in[26];

    float* out = (float*)d_out;
    float* out_lam = out + (size_t)B_ * D_ * PRED_;
    float* out_u = out_lam + (size_t)B_ * D_ * D_;

    float *t, *qkv, *y, *hp;
    __half *zh, *th, *ch, *mh, *whi, *wlo;
    cudaGetSymbolAddress((void**)&t, g_t);
    cudaGetSymbolAddress((void**)&qkv, g_qkv);
    cudaGetSymbolAddress((void**)&y, g_y);
    cudaGetSymbolAddress((void**)&hp, g_hp);
    cudaGetSymbolAddress((void**)&zh, g_zh);
    cudaGetSymbolAddress((void**)&th, g_th);
    cudaGetSymbolAddress((void**)&ch, g_ctxh);
    cudaGetSymbolAddress((void**)&mh, g_midh);
    cudaGetSymbolAddress((void**)&whi, g_whi);
    cudaGetSymbolAddress((void**)&wlo, g_wlo);

    cudaFuncSetAttribute(lam_kernel, cudaFuncAttributeMaxDynamicSharedMemorySize, 128 * 129 * 4);
    cudaFuncSetAttribute(attn_kernel, cudaFuncAttributeMaxDynamicSharedMemorySize, ATTN_SMEM);
    cudaFuncSetAttribute(gemm_mma_kernel, cudaFuncAttributeMaxDynamicSharedMemorySize, GDYN);

    const int ROWS = B_ * D_;   // 8192

    // weight conversions (fp16 hi/lo)
    auto cvt = [&](const float* src, size_t off, int n) {
        cvt_pair_kernel<<<(n / 4 + 255) / 256, 256>>>(src, whi + off, wlo + off, n / 4);
    };
    cvt(emb_w, OFF_EMB, 524288);
    cvt(qkv_w, OFF_QKV, 3145728);
    cvt(out_w, OFF_OUT, 1048576);
    cvt(ff1_w, OFF_FF1, 2097152);
    cvt(ff2_w, OFF_FF2, 2097152);
    cvt(proj_w, OFF_PROJ, 65536);

    // copula + factor MLP
    transpose_x_kernel<<<dim3(L_ / 32, D_ / 32, B_), dim3(32, 8)>>>(x);
    copula_kernel<<<B_ * D_, 1024>>>();
    mlp12_kernel<<<B_, 64>>>(mlp1_w, mlp1_b, mlp2_w, mlp2_b);
    lower_kernel<<<dim3(B_, (D_ * M_) / 256), 256>>>(mlp3_w, mlp3_b);
    lam_kernel<<<B_, 256, 128 * 129 * 4>>>(out_lam);

    // embedding: t = z @ emb_w^T + emb_b  (emit t fp32 + fp16)
    gemm_mma_kernel<<<dim3(DM_ / 128, ROWS / 128), 256, GDYN>>>(
        zh, whi + OFF_EMB, wlo + OFF_EMB, emb_b, t, th, DM_, L_, 0, 1);

    for (int l = 0; l < NL_; ++l) {
        gemm_mma_kernel<<<dim3(3 * DM_ / 128, ROWS / 128), 256, GDYN>>>(
            th, whi + OFF_QKV + (size_t)l * 3 * DM_ * DM_,
            wlo + OFF_QKV + (size_t)l * 3 * DM_ * DM_, qkv_b + (size_t)l * 3 * DM_,
            qkv, nullptr, 3 * DM_, DM_, 0, 1);
        attn_kernel<<<B_ * H_, 128, ATTN_SMEM>>>();
        gemm_mma_kernel<<<dim3(DM_ / 128, ROWS / 128), 256, GDYN>>>(
            ch, whi + OFF_OUT + (size_t)l * DM_ * DM_,
            wlo + OFF_OUT + (size_t)l * DM_ * DM_, out_b + (size_t)l * DM_,
            y, nullptr, DM_, DM_, 0, 1);
        resid_ln_kernel<<<ROWS, 128>>>(y, ln1_g + l * DM_, ln1_b + l * DM_, 1);
        gemm_mma_kernel<<<dim3(2 * DM_ / 128, ROWS / 128), 256, GDYN>>>(
            th, whi + OFF_FF1 + (size_t)l * 2 * DM_ * DM_,
            wlo + OFF_FF1 + (size_t)l * 2 * DM_ * DM_, ff1_b + (size_t)l * 2 * DM_,
            nullptr, mh, 2 * DM_, DM_, 1, 0);
        gemm_mma_kernel<<<dim3(DM_ / 128, ROWS / 128), 256, GDYN>>>(
            mh, whi + OFF_FF2 + (size_t)l * DM_ * 2 * DM_,
            wlo + OFF_FF2 + (size_t)l * DM_ * 2 * DM_, ff2_b + (size_t)l * DM_,
            y, nullptr, DM_, 2 * DM_, 0, 1);
        resid_ln_kernel<<<ROWS, 128>>>(y, ln2_g + l * DM_, ln2_b + l * DM_, 1);
    }

    // final LN (no residual) -> t + fp16
    resid_ln_kernel<<<ROWS, 128>>>(y, fn_g, fn_b, 0);

    // head projection + combine
    gemm_mma_kernel<<<dim3(M_ / 128, ROWS / 128), 256, GDYN>>>(
        th, whi + OFF_PROJ, wlo + OFF_PROJ, proj_b, hp, nullptr, M_, DM_, 0, 1);
    head_kernel<<<ROWS, 128>>>(u, hbias, out_lam, out);

    // u passthrough
    cudaMemcpyAsync(out_u, u, (size_t)D_ * M_ * sizeof(float), cudaMemcpyDeviceToDevice);
}

// round 7
// speedup vs baseline: 2.6493x; 1.1358x over previous
#include <cuda_runtime.h>
#include <cuda_fp16.h>
#include <cstdint>
#include <math.h>

#define B_    64
#define L_    1024
#define D_    128
#define M_    128
#define DM_   512
#define NL_   4
#define H_    8
#define DH_   64
#define PRED_ 96

// ================= helpers =================
__device__ __forceinline__ uint32_t smem_to_u32(const void* smem_ptr) {
    uint32_t addr;
    asm("{ .reg .u64 tmp; cvta.to.shared.u64 tmp, %1; cvt.u32.u64 %0, tmp; }"
        : "=r"(addr) : "l"(smem_ptr));
    return addr;
}
__device__ __forceinline__ void ldsm_x4(uint32_t& r0, uint32_t& r1, uint32_t& r2,
                                        uint32_t& r3, uint32_t addr) {
    asm volatile("ldmatrix.sync.aligned.m8n8.x4.shared.b16 {%0,%1,%2,%3}, [%4];"
                 : "=r"(r0), "=r"(r1), "=r"(r2), "=r"(r3) : "r"(addr));
}
__device__ __forceinline__ void mma_f16(float* d, const uint32_t* a, const uint32_t* b) {
    asm volatile(
        "mma.sync.aligned.m16n8k16.row.col.f32.f16.f16.f32 "
        "{%0,%1,%2,%3}, {%4,%5,%6,%7}, {%8,%9}, {%0,%1,%2,%3};"
        : "+f"(d[0]), "+f"(d[1]), "+f"(d[2]), "+f"(d[3])
        : "r"(a[0]), "r"(a[1]), "r"(a[2]), "r"(a[3]), "r"(b[0]), "r"(b[1]));
}
__device__ __forceinline__ void cp_async16(uint32_t saddr, const void* gptr) {
    asm volatile("cp.async.cg.shared.global [%0], [%1], 16;" :: "r"(saddr), "l"(gptr));
}
__device__ __forceinline__ void cp_commit() {
    asm volatile("cp.async.commit_group;" ::: "memory");
}
template<int N> __device__ __forceinline__ void cp_wait() {
    asm volatile("cp.async.wait_group %0;" :: "n"(N) : "memory");
}
// packed fp32x2
typedef unsigned long long u64t;
__device__ __forceinline__ u64t pk2(float a, float b) {
    u64t r; asm("mov.b64 %0, {%1, %2};" : "=l"(r) : "f"(a), "f"(b)); return r;
}
__device__ __forceinline__ void upk2(u64t x, float& a, float& b) {
    asm("mov.b64 {%0, %1}, %2;" : "=f"(a), "=f"(b) : "l"(x));
}
__device__ __forceinline__ u64t fma2(u64t a, u64t b, u64t c) {
    u64t d; asm("fma.rn.f32x2 %0, %1, %2, %3;" : "=l"(d) : "l"(a), "l"(b), "l"(c));
    return d;
}

// ---------------- scratch (device globals; no allocation) ----------------
__device__ float g_xt[(size_t)B_ * D_ * L_];
__device__ float g_s[B_ * 2 * D_];
__device__ float g_h2[B_ * 32];
__device__ float g_lower[(size_t)B_ * D_ * M_];
__device__ float g_t[(size_t)B_ * D_ * DM_];          // backbone state fp32
__device__ float g_qkv[(size_t)B_ * D_ * 3 * DM_];
__device__ float g_y[(size_t)B_ * D_ * DM_];
__device__ float g_hp[(size_t)B_ * D_ * M_];

// fp16 single activation buffers
__device__ __half g_zh[(size_t)B_ * D_ * L_];
__device__ __half g_th[(size_t)B_ * D_ * DM_];
__device__ __half g_ctxh[(size_t)B_ * D_ * DM_];
__device__ __half g_midh[(size_t)B_ * D_ * 2 * DM_];

// fp16 hi/lo weight buffers (packed)
#define OFF_EMB  0
#define OFF_QKV  524288
#define OFF_OUT  3670016
#define OFF_FF1  4718592
#define OFF_FF2  6815744
#define OFF_PROJ 8912896
#define W_TOTAL  8978432
__device__ __half g_whi[W_TOTAL];
__device__ __half g_wlo[W_TOTAL];

// ---------------- all-weights fp32 -> (hi, lo) fp16 conversion (one launch) ----------------
// i4 prefix bounds: emb 131072 | qkv 786432 | out 262144 | ff1 524288 | ff2 524288 | proj 16384
__global__ void cvt_all_kernel(const float* __restrict__ s0, const float* __restrict__ s1,
                               const float* __restrict__ s2, const float* __restrict__ s3,
                               const float* __restrict__ s4, const float* __restrict__ s5) {
    int gid = blockIdx.x * 256 + threadIdx.x;
    if (gid >= 2244608) return;
    const float* src; size_t off; int local;
    if (gid < 131072)       { src = s0; off = OFF_EMB;  local = gid; }
    else if (gid < 917504)  { src = s1; off = OFF_QKV;  local = gid - 131072; }
    else if (gid < 1179648) { src = s2; off = OFF_OUT;  local = gid - 917504; }
    else if (gid < 1703936) { src = s3; off = OFF_FF1;  local = gid - 1179648; }
    else if (gid < 2228224) { src = s4; off = OFF_FF2;  local = gid - 1703936; }
    else                    { src = s5; off = OFF_PROJ; local = gid - 2228224; }
    float4 f = ((const float4*)src)[local];
    __half h0 = __float2half(f.x), h1 = __float2half(f.y);
    __half h2 = __float2half(f.z), h3 = __float2half(f.w);
    __half2* hp = (__half2*)(g_whi + off);
    __half2* lp = (__half2*)(g_wlo + off);
    hp[2 * local] = __half2(h0, h1);
    hp[2 * local + 1] = __half2(h2, h3);
    lp[2 * local] = __half2(__float2half(f.x - __half2float(h0)),
                            __float2half(f.y - __half2float(h1)));
    lp[2 * local + 1] = __half2(__float2half(f.z - __half2float(h2)),
                                __float2half(f.w - __half2float(h3)));
}

// ---------------- transpose x [B,L,D] -> g_xt [B,D,L] ----------------
__global__ void transpose_x_kernel(const float* __restrict__ x) {
    __shared__ float tile[32][33];
    int b = blockIdx.z;
    int l0 = blockIdx.x * 32, d0 = blockIdx.y * 32;
    int lx = threadIdx.x, ly = threadIdx.y;
#pragma unroll
    for (int r = 0; r < 32; r += 8)
        tile[ly + r][lx] = x[((size_t)b * L_ + (l0 + ly + r)) * D_ + (d0 + lx)];
    __syncthreads();
#pragma unroll
    for (int r = 0; r < 32; r += 8)
        g_xt[((size_t)b * D_ + (d0 + ly + r)) * L_ + (l0 + lx)] = tile[lx][ly + r];
}

// ---------------- copula: hybrid shfl/smem bitonic rank -> erfinv z (fp16) ----------------
__global__ __launch_bounds__(1024) void copula_kernel() {
    __shared__ float vals[L_];
    __shared__ int   idxs[L_];
    __shared__ float sq[L_];

    int blk = blockIdx.x;
    int tid = threadIdx.x;
    const float* col = g_xt + (size_t)blk * L_;

    float v = col[tid];
    int   i = tid;

    // register-only phases (partner within warp): k = 2..32
#pragma unroll
    for (int k = 2; k <= 32; k <<= 1) {
#pragma unroll
        for (int j = k >> 1; j > 0; j >>= 1) {
            float vo = __shfl_xor_sync(0xffffffffu, v, j);
            int   io = __shfl_xor_sync(0xffffffffu, i, j);
            bool up = ((tid & k) == 0);
            bool low = ((tid & j) == 0);
            float vl = low ? v : vo, vh = low ? vo : v;
            int   il = low ? i : io, ih = low ? io : i;
            bool gt = (vl > vh) || (vl == vh && il > ih);
            if (gt == up) { v = vo; i = io; }
        }
    }
    // k = 64..1024: smem stages for j>=32, shfl stages for j<=16
    for (int k = 64; k <= 1024; k <<= 1) {
        vals[tid] = v; idxs[tid] = i;
        __syncthreads();
        for (int j = k >> 1; j >= 32; j >>= 1) {
            int ixj = tid ^ j;
            if (ixj > tid) {
                bool up = ((tid & k) == 0);
                float v1 = vals[tid], v2 = vals[ixj];
                int   i1 = idxs[tid], i2 = idxs[ixj];
                bool gt = (v1 > v2) || (v1 == v2 && i1 > i2);
                if (gt == up) {
                    vals[tid] = v2; vals[ixj] = v1;
                    idxs[tid] = i2; idxs[ixj] = i1;
                }
            }
            __syncthreads();
        }
        v = vals[tid]; i = idxs[tid];
#pragma unroll
        for (int j = 16; j > 0; j >>= 1) {
            float vo = __shfl_xor_sync(0xffffffffu, v, j);
            int   io = __shfl_xor_sync(0xffffffffu, i, j);
            bool up = ((tid & k) == 0);
            bool low = ((tid & j) == 0);
            float vl = low ? v : vo, vh = low ? vo : v;
            int   il = low ? i : io, ih = low ? io : i;
            bool gt = (vl > vh) || (vl == vh && il > ih);
            if (gt == up) { v = vo; i = io; }
        }
    }
    // rank scatter: element with original index i sits at sorted position tid
    __syncthreads();
    idxs[i] = tid;
    __syncthreads();

    int r = idxs[tid];
    float u = ((float)(r + 1) + 0.5f) * (1.0f / (float)L_);
    u = fminf(fmaxf(u, 1e-6f), 1.0f - 1e-6f);
    float zv = erfinvf(2.0f * u - 1.0f) * 1.41421356237309515f;
    g_zh[(size_t)blk * L_ + tid] = __float2half(zv);

    __syncthreads();
    vals[tid] = zv;
    sq[tid] = zv * zv;
    __syncthreads();
    for (int s = 512; s > 0; s >>= 1) {
        if (tid < s) { vals[tid] += vals[tid + s]; sq[tid] += sq[tid + s]; }
        __syncthreads();
    }
    if (tid == 0) {
        float sum = vals[0], ssq = sq[0];
        float mean = sum * (1.0f / (float)L_);
        float var = (ssq - sum * sum * (1.0f / (float)L_)) * (1.0f / (float)(L_ - 1));
        int b = blk / D_, d = blk % D_;
        g_s[b * 2 * D_ + d] = mean;
        g_s[b * 2 * D_ + D_ + d] = sqrtf(fmaxf(var, 0.0f));
    }
}

// ---------------- s -> relu(mlp1) -> relu(mlp2) -> g_h2 ----------------
__global__ void mlp12_kernel(const float* __restrict__ w1, const float* __restrict__ b1,
                             const float* __restrict__ w2, const float* __restrict__ b2) {
    __shared__ float srow[2 * D_];
    __shared__ float h1[64];
    int b = blockIdx.x, tid = threadIdx.x;
    for (int i = tid; i < 2 * D_; i += 64) srow[i] = g_s[b * 2 * D_ + i];
    __syncthreads();
    float acc = b1[tid];
    for (int k = 0; k < 2 * D_; ++k) acc += srow[k] * w1[tid * 2 * D_ + k];
    h1[tid] = fmaxf(acc, 0.0f);
    __syncthreads();
    if (tid < 32) {
        float a2 = b2[tid];
        for (int k = 0; k < 64; ++k) a2 += h1[k] * w2[tid * 64 + k];
        g_h2[b * 32 + tid] = fmaxf(a2, 0.0f);
    }
}

// ---------------- lower = h2 @ mlp3_w^T + b ----------------
__global__ __launch_bounds__(256) void lower_kernel(const float* __restrict__ w3,
                                                    const float* __restrict__ b3) {
    __shared__ float h2s[32];
    __shared__ float wt[256][33];
    int b = blockIdx.x;
    int j0 = blockIdx.y * 256;
    int tid = threadIdx.x;
    if (tid < 32) h2s[tid] = g_h2[b * 32 + tid];
    for (int i = tid; i < 256 * 32; i += 256) {
        int rr = i >> 5, cc = i & 31;
        wt[rr][cc] = w3[(size_t)j0 * 32 + i];
    }
    __syncthreads();
    float acc = b3[j0 + tid];
#pragma unroll
    for (int k = 0; k < 32; ++k) acc += h2s[k] * wt[tid][k];
    g_lower[(size_t)b * (D_ * M_) + j0 + tid] = acc;
}

// ---------------- lam[b] = lower[b] @ lower[b]^T  (into d_out) ----------------
__global__ __launch_bounds__(256) void lam_kernel(float* __restrict__ lam_out) {
    extern __shared__ float low[];   // [128][129]
    int b = blockIdx.x, tid = threadIdx.x;
    for (int i = tid; i < D_ * M_; i += 256) {
        int rr = i >> 7, cc = i & 127;
        low[rr * 129 + cc] = g_lower[(size_t)b * (D_ * M_) + i];
    }
    __syncthreads();
    for (int e = tid; e < D_ * D_; e += 256) {
        int i = e >> 7, j = e & 127;
        const float* ri = &low[i * 129];
        const float* rj = &low[j * 129];
        float acc = 0.0f;
#pragma unroll 8
        for (int m = 0; m < M_; ++m) acc += ri[m] * rj[m];
        lam_out[(size_t)b * D_ * D_ + e] = acc;
    }
}

// ================= pipelined mma.sync fp16x2 NT GEMM (unchanged from R6) =================
#define STAGES 4
#define STG_BYTES 24576
#define GDYN (STAGES * STG_BYTES + 1024)
__global__ __launch_bounds__(256, 2) void gemm_mma_kernel(
    const __half* __restrict__ Ah,
    const __half* __restrict__ Whi, const __half* __restrict__ Wlo,
    const float* __restrict__ bias, float* __restrict__ C,
    __half* __restrict__ Ch,
    int Ndim, int Kdim, int relu, int writeC)
{
    extern __shared__ char dsm_raw[];
    uint32_t dsm_u0 = smem_to_u32(dsm_raw);
    uint32_t base_u = (dsm_u0 + 1023u) & ~1023u;
    int tid = threadIdx.x;
    int wid = tid >> 5, lane = tid & 31;
    int n0 = blockIdx.x * 128, m0 = blockIdx.y * 128;
    int wm = (wid & 3) * 32;
    int wn = (wid >> 2) * 64;

    float acc[2][8][4];
#pragma unroll
    for (int a = 0; a < 2; ++a)
#pragma unroll
        for (int b = 0; b < 8; ++b)
#pragma unroll
            for (int c = 0; c < 4; ++c) acc[a][b][c] = 0.0f;

    int nch = Kdim >> 5;

    auto stage_fill = [&](int ch, int stg) {
        int k0 = ch << 5;
        uint32_t sb = base_u + stg * STG_BYTES;
#pragma unroll
        for (int t = 0; t < 6; ++t) {
            int idx = tid + t * 256;
            int tensor = idx >> 9;
            int r = (idx >> 2) & 127;
            int cs = idx & 3;
            const __half* g;
            if (tensor == 0) g = Ah; else if (tensor == 1) g = Whi; else g = Wlo;
            int rr = ((tensor == 0) ? m0 : n0) + r;
            g += (size_t)rr * Kdim + k0 + cs * 8;
            uint32_t off = (uint32_t)(r * 64 + cs * 16);
            uint32_t sw = off ^ ((off >> 3) & 0x30);
            cp_async16(sb + tensor * 8192 + sw, g);
        }
        cp_commit();
    };

    stage_fill(0, 0);
    stage_fill(1, 1);
    stage_fill(2, 2);

    for (int ch = 0; ch < nch; ++ch) {
        int rem = nch - ch;
        if (rem >= 3) cp_wait<2>();
        else if (rem == 2) cp_wait<1>();
        else cp_wait<0>();
        __syncthreads();
        if (ch + 3 < nch) stage_fill(ch + 3, (ch + 3) % STAGES);

        uint32_t sb = base_u + (ch % STAGES) * STG_BYTES;
#pragma unroll
        for (int s = 0; s < 2; ++s) {
            uint32_t af[2][4];
#pragma unroll
            for (int mt = 0; mt < 2; ++mt) {
                uint32_t off = (uint32_t)((wm + mt * 16 + (lane & 15)) * 64
                                          + s * 32 + ((lane >> 4) << 4));
                uint32_t sw = off ^ ((off >> 3) & 0x30);
                ldsm_x4(af[mt][0], af[mt][1], af[mt][2], af[mt][3], sb + sw);
            }
#pragma unroll
            for (int p = 0; p < 4; ++p) {
                uint32_t off = (uint32_t)((wn + p * 16 + ((lane >> 3) & 1) * 8 + (lane & 7)) * 64
                                          + s * 32 + ((lane >> 4) << 4));
                uint32_t sw = off ^ ((off >> 3) & 0x30);
                uint32_t bh[4], bl[4];
                ldsm_x4(bh[0], bh[1], bh[2], bh[3], sb + 8192 + sw);
                ldsm_x4(bl[0], bl[1], bl[2], bl[3], sb + 16384 + sw);
                uint32_t bh0[2] = {bh[0], bh[2]}, bh1[2] = {bh[1], bh[3]};
                uint32_t bl0[2] = {bl[0], bl[2]}, bl1[2] = {bl[1], bl[3]};
#pragma unroll
                for (int mt = 0; mt < 2; ++mt) {
                    mma_f16(acc[mt][2 * p],     af[mt], bh0);
                    mma_f16(acc[mt][2 * p + 1], af[mt], bh1);
                    mma_f16(acc[mt][2 * p],     af[mt], bl0);
                    mma_f16(acc[mt][2 * p + 1], af[mt], bl1);
                }
            }
        }
    }

    int r4 = lane >> 2, c2 = (lane & 3) * 2;
#pragma unroll
    for (int mt = 0; mt < 2; ++mt) {
        int row0 = m0 + wm + mt * 16 + r4;
#pragma unroll
        for (int nb = 0; nb < 8; ++nb) {
            int col = n0 + wn + nb * 8 + c2;
            float bx = bias[col], by = bias[col + 1];
            float2 v0 = {acc[mt][nb][0] + bx, acc[mt][nb][1] + by};
            float2 v1 = {acc[mt][nb][2] + bx, acc[mt][nb][3] + by};
            if (relu) {
                v0.x = fmaxf(v0.x, 0.f); v0.y = fmaxf(v0.y, 0.f);
                v1.x = fmaxf(v1.x, 0.f); v1.y = fmaxf(v1.y, 0.f);
            }
            size_t i0 = (size_t)row0 * Ndim + col;
            size_t i1 = (size_t)(row0 + 8) * Ndim + col;
            if (writeC) {
                *(float2*)&C[i0] = v0;
                *(float2*)&C[i1] = v1;
            }
            if (Ch) {
                *(__half2*)&Ch[i0] = __half2(__float2half(v0.x), __float2half(v0.y));
                *(__half2*)&Ch[i1] = __half2(__float2half(v1.x), __float2half(v1.y));
            }
        }
    }
}

// ---------------- fused attention per (b,h), 256 threads, f32x2, register scores ----------------
// thread (row = tid&127, jh = tid>>7): scores for j in [jh*64, jh*64+64), partner-reduced softmax,
// ctx partial sums combined through smem. smem: ks[128][68] + vs[128][68] + cb[128][36].
#define KROW 68
#define CBROW 36
#define ATTN_SMEM ((128 * KROW * 2 + 128 * CBROW) * 4)
__global__ __launch_bounds__(256, 2) void attn_kernel() {
    extern __shared__ float sm[];
    float* ks = sm;
    float* vs = sm + 128 * KROW;
    float* cb = sm + 2 * 128 * KROW;

    int bh = blockIdx.x;
    int b = bh >> 3, h = bh & 7;
    int tid = threadIdx.x;
    int row = tid & 127, jh = tid >> 7;
    const float* qkvb = g_qkv + (size_t)b * D_ * 3 * DM_;

    // fill K/V halves (each thread: 32 floats of its row)
    const float* krow = qkvb + (size_t)row * 3 * DM_ + DM_ + h * DH_ + jh * 32;
    const float* vrow = qkvb + (size_t)row * 3 * DM_ + 2 * DM_ + h * DH_ + jh * 32;
#pragma unroll
    for (int c = 0; c < 32; c += 4) {
        *(float4*)&ks[row * KROW + jh * 32 + c] = *(const float4*)(krow + c);
        *(float4*)&vs[row * KROW + jh * 32 + c] = *(const float4*)(vrow + c);
    }
    __syncthreads();

    // scores (packed f32x2), q cached 16 pairs per half-pass
    float s[64];
    const float* qrow = qkvb + (size_t)row * 3 * DM_ + h * DH_;
#pragma unroll
    for (int ch2 = 0; ch2 < 2; ++ch2) {
        u64t q2[16];
        const u64t* q64 = (const u64t*)(qrow + ch2 * 32);
#pragma unroll
        for (int c = 0; c < 16; ++c) q2[c] = q64[c];
#pragma unroll 4
        for (int j0 = 0; j0 < 64; ++j0) {
            int jg = jh * 64 + j0;
            const u64t* k64 = (const u64t*)&ks[jg * KROW + ch2 * 32];
            u64t a2 = pk2(0.f, 0.f);
#pragma unroll
            for (int c = 0; c < 16; ++c) a2 = fma2(q2[c], k64[c], a2);
            float ax, ay; upk2(a2, ax, ay);
            s[j0] = (ch2 ? s[j0] : 0.0f) + ax + ay;
        }
    }
    // local max
    float mx = -1e30f;
#pragma unroll
    for (int j = 0; j < 64; ++j) { s[j] *= 0.125f; mx = fmaxf(mx, s[j]); }
    cb[jh * 128 + row] = mx;
    __syncthreads();
    mx = fmaxf(cb[row], cb[128 + row]);
    float lsum = 0.0f;
#pragma unroll
    for (int j = 0; j < 64; ++j) { s[j] = __expf(s[j] - mx); lsum += s[j]; }
    cb[256 + jh * 128 + row] = lsum;
    __syncthreads();
    float inv = 1.0f / (cb[256 + row] + cb[384 + row]);
#pragma unroll
    for (int j = 0; j < 64; ++j) s[j] *= inv;

    // ctx: two c-passes of 32 columns; partner partials combined through cb
#pragma unroll
    for (int cp = 0; cp < 2; ++cp) {
        u64t a2[16];
#pragma unroll
        for (int c = 0; c < 16; ++c) a2[c] = pk2(0.f, 0.f);
#pragma unroll 4
        for (int j0 = 0; j0 < 64; ++j0) {
            int jg = jh * 64 + j0;
            u64t p2 = pk2(s[j0], s[j0]);
            const u64t* v64 = (const u64t*)&vs[jg * KROW + cp * 32];
#pragma unroll
            for (int c = 0; c < 16; ++c) a2[c] = fma2(p2, v64[c], a2[c]);
        }
        __syncthreads();   // cb free (prev use done) before jh0 writes
        if (jh == 0) {
#pragma unroll
            for (int c = 0; c < 16; ++c) {
                float ax, ay; upk2(a2[c], ax, ay);
                cb[row * CBROW + 2 * c] = ax;
                cb[row * CBROW + 2 * c + 1] = ay;
            }
        }
        __syncthreads();
        if (jh == 1) {
            size_t obase = ((size_t)b * D_ + row) * DM_ + h * DH_ + cp * 32;
#pragma unroll
            for (int c = 0; c < 16; ++c) {
                float ax, ay; upk2(a2[c], ax, ay);
                float fx = ax + cb[row * CBROW + 2 * c];
                float fy = ay + cb[row * CBROW + 2 * c + 1];
                *(__half2*)&g_ctxh[obase + 2 * c] = __floats2half2_rn(fx, fy);
            }
        }
    }
}

// ---------------- residual + layernorm (in-place on g_t, emits fp16) ----------------
__global__ __launch_bounds__(128) void resid_ln_kernel(const float* __restrict__ y,
                                                       const float* __restrict__ gam,
                                                       const float* __restrict__ bet,
                                                       int has_res) {
    int row = blockIdx.x, tid = threadIdx.x;
    float* trow = g_t + (size_t)row * DM_;
    const float* yrow = y + (size_t)row * DM_;
    float v[4];
    float s = 0.0f, sq = 0.0f;
#pragma unroll
    for (int r = 0; r < 4; ++r) {
        int c = tid + r * 128;
        float val = trow[c];
        if (has_res) val += yrow[c];
        v[r] = val; s += val; sq += val * val;
    }
    __shared__ float rs[4], rq[4];
    unsigned lane = tid & 31, wid = tid >> 5;
#pragma unroll
    for (int off = 16; off; off >>= 1) {
        s += __shfl_down_sync(0xffffffffu, s, off);
        sq += __shfl_down_sync(0xffffffffu, sq, off);
    }
    if (lane == 0) { rs[wid] = s; rq[wid] = sq; }
    __syncthreads();
    float S = rs[0] + rs[1] + rs[2] + rs[3];
    float SQ = rq[0] + rq[1] + rq[2] + rq[3];
    float mean = S * (1.0f / (float)DM_);
    float var = SQ * (1.0f / (float)DM_) - mean * mean;
    float rstd = rsqrtf(var + 1e-5f);
#pragma unroll
    for (int r = 0; r < 4; ++r) {
        int c = tid + r * 128;
        float o = (v[r] - mean) * rstd * gam[c] + bet[c];
        trow[c] = o;
        g_th[(size_t)row * DM_ + c] = __float2half(o);
    }
}

// ---------------- head ----------------
__global__ __launch_bounds__(128) void head_kernel(const float* __restrict__ u,
                                                   const float* __restrict__ head_bias,
                                                   const float* __restrict__ lam,
                                                   float* __restrict__ out_y) {
    __shared__ float hps[M_];
    __shared__ float red[4];
    __shared__ float ybc;
    int blk = blockIdx.x;
    int b = blk >> 7, i = blk & 127;
    int tid = threadIdx.x;
    hps[tid] = g_hp[(size_t)blk * M_ + tid];
    __syncthreads();
    const float* lamb = lam + (size_t)b * D_ * D_;
    float acc = 0.0f;
    for (int k = 0; k < D_; ++k) acc += hps[k] * lamb[(size_t)k * D_ + tid];
    float p = acc * u[(size_t)i * M_ + tid];
    unsigned lane = tid & 31, wid = tid >> 5;
#pragma unroll
    for (int off = 16; off; off >>= 1) p += __shfl_down_sync(0xffffffffu, p, off);
    if (lane == 0) red[wid] = p;
    __syncthreads();
    if (tid == 0) ybc = red[0] + red[1] + red[2] + red[3] + head_bias[i];
    __syncthreads();
    float yv = ybc;
    if (tid < PRED_) out_y[(size_t)blk * PRED_ + tid] = yv;
}

// ---------------- host launcher ----------------
extern "C" void kernel_launch(void* const* d_in, const int* in_sizes, int n_in,
                              void* d_out, int out_size) {
    const float* x      = (const float*)d_in[0];
    const float* emb_w  = (const float*)d_in[1];
    const float* emb_b  = (const float*)d_in[2];
    const float* qkv_w  = (const float*)d_in[3];
    const float* qkv_b  = (const float*)d_in[4];
    const float* out_w  = (const float*)d_in[5];
    const float* out_b  = (const float*)d_in[6];
    const float* ln1_g  = (const float*)d_in[7];
    const float* ln1_b  = (const float*)d_in[8];
    const float* ln2_g  = (const float*)d_in[9];
    const float* ln2_b  = (const float*)d_in[10];
    const float* ff1_w  = (const float*)d_in[11];
    const float* ff1_b  = (const float*)d_in[12];
    const float* ff2_w  = (const float*)d_in[13];
    const float* ff2_b  = (const float*)d_in[14];
    const float* fn_g   = (const float*)d_in[15];
    const float* fn_b   = (const float*)d_in[16];
    const float* mlp1_w = (const float*)d_in[17];
    const float* mlp1_b = (const float*)d_in[18];
    const float* mlp2_w = (const float*)d_in[19];
    const float* mlp2_b = (const float*)d_in[20];
    const float* mlp3_w = (const float*)d_in[21];
    const float* mlp3_b = (const float*)d_in[22];
    const float* proj_w = (const float*)d_in[23];
    const float* proj_b = (const float*)d_in[24];
    const float* u      = (const float*)d_in[25];
    const float* hbias  = (const float*)d_in[26];

    float* out = (float*)d_out;
    float* out_lam = out + (size_t)B_ * D_ * PRED_;
    float* out_u = out_lam + (size_t)B_ * D_ * D_;

    float *t, *qkv, *y, *hp;
    __half *zh, *th, *ch, *mh, *whi, *wlo;
    cudaGetSymbolAddress((void**)&t, g_t);
    cudaGetSymbolAddress((void**)&qkv, g_qkv);
    cudaGetSymbolAddress((void**)&y, g_y);
    cudaGetSymbolAddress((void**)&hp, g_hp);
    cudaGetSymbolAddress((void**)&zh, g_zh);
    cudaGetSymbolAddress((void**)&th, g_th);
    cudaGetSymbolAddress((void**)&ch, g_ctxh);
    cudaGetSymbolAddress((void**)&mh, g_midh);
    cudaGetSymbolAddress((void**)&whi, g_whi);
    cudaGetSymbolAddress((void**)&wlo, g_wlo);

    cudaFuncSetAttribute(lam_kernel, cudaFuncAttributeMaxDynamicSharedMemorySize, 128 * 129 * 4);
    cudaFuncSetAttribute(attn_kernel, cudaFuncAttributeMaxDynamicSharedMemorySize, ATTN_SMEM);
    cudaFuncSetAttribute(gemm_mma_kernel, cudaFuncAttributeMaxDynamicSharedMemorySize, GDYN);

    const int ROWS = B_ * D_;   // 8192

    // all weight conversions in one launch
    cvt_all_kernel<<<(2244608 + 255) / 256, 256>>>(emb_w, qkv_w, out_w, ff1_w, ff2_w, proj_w);

    // copula + factor MLP
    transpose_x_kernel<<<dim3(L_ / 32, D_ / 32, B_), dim3(32, 8)>>>(x);
    copula_kernel<<<B_ * D_, 1024>>>();
    mlp12_kernel<<<B_, 64>>>(mlp1_w, mlp1_b, mlp2_w, mlp2_b);
    lower_kernel<<<dim3(B_, (D_ * M_) / 256), 256>>>(mlp3_w, mlp3_b);
    lam_kernel<<<B_, 256, 128 * 129 * 4>>>(out_lam);

    // embedding: t = z @ emb_w^T + emb_b  (emit t fp32 + fp16)
    gemm_mma_kernel<<<dim3(DM_ / 128, ROWS / 128), 256, GDYN>>>(
        zh, whi + OFF_EMB, wlo + OFF_EMB, emb_b, t, th, DM_, L_, 0, 1);

    for (int l = 0; l < NL_; ++l) {
        gemm_mma_kernel<<<dim3(3 * DM_ / 128, ROWS / 128), 256, GDYN>>>(
            th, whi + OFF_QKV + (size_t)l * 3 * DM_ * DM_,
            wlo + OFF_QKV + (size_t)l * 3 * DM_ * DM_, qkv_b + (size_t)l * 3 * DM_,
            qkv, nullptr, 3 * DM_, DM_, 0, 1);
        attn_kernel<<<B_ * H_, 256, ATTN_SMEM>>>();
        gemm_mma_kernel<<<dim3(DM_ / 128, ROWS / 128), 256, GDYN>>>(
            ch, whi + OFF_OUT + (size_t)l * DM_ * DM_,
            wlo + OFF_OUT + (size_t)l * DM_ * DM_, out_b + (size_t)l * DM_,
            y, nullptr, DM_, DM_, 0, 1);
        resid_ln_kernel<<<ROWS, 128>>>(y, ln1_g + l * DM_, ln1_b + l * DM_, 1);
        gemm_mma_kernel<<<dim3(2 * DM_ / 128, ROWS / 128), 256, GDYN>>>(
            th, whi + OFF_FF1 + (size_t)l * 2 * DM_ * DM_,
            wlo + OFF_FF1 + (size_t)l * 2 * DM_ * DM_, ff1_b + (size_t)l * 2 * DM_,
            nullptr, mh, 2 * DM_, DM_, 1, 0);
        gemm_mma_kernel<<<dim3(DM_ / 128, ROWS / 128), 256, GDYN>>>(
            mh, whi + OFF_FF2 + (size_t)l * DM_ * 2 * DM_,
            wlo + OFF_FF2 + (size_t)l * DM_ * 2 * DM_, ff2_b + (size_t)l * DM_,
            y, nullptr, DM_, 2 * DM_, 0, 1);
        resid_ln_kernel<<<ROWS, 128>>>(y, ln2_g + l * DM_, ln2_b + l * DM_, 1);
    }

    // final LN (no residual) -> t + fp16
    resid_ln_kernel<<<ROWS, 128>>>(y, fn_g, fn_b, 0);

    // head projection + combine
    gemm_mma_kernel<<<dim3(M_ / 128, ROWS / 128), 256, GDYN>>>(
        th, whi + OFF_PROJ, wlo + OFF_PROJ, proj_b, hp, nullptr, M_, DM_, 0, 1);
    head_kernel<<<ROWS, 128>>>(u, hbias, out_lam, out);

    // u passthrough
    cudaMemcpyAsync(out_u, u, (size_t)D_ * M_ * sizeof(float), cudaMemcpyDeviceToDevice);
}